// round 9
// baseline (speedup 1.0000x reference)
#include <cuda_runtime.h>
#include <cuda_fp16.h>
#include <cstdint>
#include <math.h>

// Problem constants
#define T_TOK 1024
#define H_DIM 1024
#define I_DIM 512
#define N_EXP 16
#define TOPK  4
#define NPAIR (T_TOK * TOPK)   // 4096

// ============================================================================
// Scratch (__device__ globals; allocations are forbidden)
// ============================================================================
__device__ int g_offset[N_EXP + 1];
__device__ int g_tok[NPAIR];
__device__ int g_pos_of[NPAIR];

__device__ __half g_Xh[T_TOK * H_DIM];               // hidden, fp16
__device__ __half g_GUh[N_EXP * 2 * I_DIM * H_DIM];  // gate_up, fp16
__device__ __half g_Dh[N_EXP * H_DIM * I_DIM];       // down, fp16
__device__ __half g_Hh[NPAIR * I_DIM];               // silu(g)*u, fp16
__device__ float  g_pout[NPAIR * H_DIM];

// ============================================================================
// PTX helpers (sm_80-era: cp.async, ldmatrix, mma.sync — legal on compute_103)
// ============================================================================
__device__ __forceinline__ uint32_t smem_to_u32(const void* p) {
    uint32_t a;
    asm("{ .reg .u64 t; cvta.to.shared.u64 t, %1; cvt.u32.u64 %0, t; }" : "=r"(a) : "l"(p));
    return a;
}
__device__ __forceinline__ void cp16(uint32_t saddr, const void* g, int szbytes) {
    asm volatile("cp.async.cg.shared.global [%0], [%1], 16, %2;"
                 :: "r"(saddr), "l"(g), "r"(szbytes) : "memory");
}
#define CP_COMMIT() asm volatile("cp.async.commit_group;" ::: "memory")
#define CP_WAIT1()  asm volatile("cp.async.wait_group 1;" ::: "memory")
#define CP_WAIT0()  asm volatile("cp.async.wait_group 0;" ::: "memory")

__device__ __forceinline__ void ldsm_x4(uint32_t* r, uint32_t addr) {
    asm volatile("ldmatrix.sync.aligned.m8n8.x4.shared.b16 {%0,%1,%2,%3}, [%4];"
                 : "=r"(r[0]), "=r"(r[1]), "=r"(r[2]), "=r"(r[3]) : "r"(addr));
}
__device__ __forceinline__ void mma16816(float* c, const uint32_t* a, uint32_t b0, uint32_t b1) {
    asm volatile(
        "mma.sync.aligned.m16n8k16.row.col.f32.f16.f16.f32 "
        "{%0,%1,%2,%3}, {%4,%5,%6,%7}, {%8,%9}, {%0,%1,%2,%3};"
        : "+f"(c[0]), "+f"(c[1]), "+f"(c[2]), "+f"(c[3])
        : "r"(a[0]), "r"(a[1]), "r"(a[2]), "r"(a[3]), "r"(b0), "r"(b1));
}

// Tile smem: [128 rows][32 fp16] = 64B/row, 4x 16B chunks/row, chunk' = chunk ^ (row&3)
// Stage: A | B (2 x 8KB = 16KB), double-buffered 32KB (both GEMMs)
#define SA    0
#define SBH   8192
#define G_ST  16384
#define G_TOTAL (2 * G_ST)

// ============================================================================
// Routing: single-block count -> prefix -> scatter (1 launch)
// ============================================================================
__global__ void routing_kernel(const int* __restrict__ idx) {
    __shared__ int cnt[N_EXP];
    __shared__ int off[N_EXP];
    const int tid = threadIdx.x;   // 256 threads
    if (tid < N_EXP) cnt[tid] = 0;
    __syncthreads();
    #pragma unroll
    for (int j = 0; j < NPAIR / 256; j++)
        atomicAdd(&cnt[idx[tid + j * 256]], 1);
    __syncthreads();
    if (tid == 0) {
        int acc = 0;
        for (int e = 0; e < N_EXP; e++) { off[e] = acc; g_offset[e] = acc; acc += cnt[e]; }
        g_offset[N_EXP] = acc;
    }
    __syncthreads();
    if (tid < N_EXP) cnt[tid] = 0;
    __syncthreads();
    #pragma unroll
    for (int j = 0; j < NPAIR / 256; j++) {
        const int i = tid + j * 256;
        const int e = idx[i];
        const int pos = off[e] + atomicAdd(&cnt[e], 1);
        g_tok[pos]  = i >> 2;
        g_pos_of[i] = pos;
    }
}

// ============================================================================
// Fused fp32 -> fp16 convert: gate_up, down, hidden (hi only, 1 launch)
// ============================================================================
#define N4G (N_EXP * 2 * I_DIM * H_DIM / 4)   // 4194304
#define N4D (N_EXP * H_DIM * I_DIM / 4)       // 2097152
#define N4X (T_TOK * H_DIM / 4)               // 262144
__global__ void split_all_kernel(const float* __restrict__ gu,
                                 const float* __restrict__ dn,
                                 const float* __restrict__ x) {
    const int i = blockIdx.x * blockDim.x + threadIdx.x;
    const float* src;
    __half* hi;
    int j;
    if (i < N4G)                  { src = gu; j = i;             hi = g_GUh; }
    else if (i < N4G + N4D)       { src = dn; j = i - N4G;       hi = g_Dh;  }
    else if (i < N4G + N4D + N4X) { src = x;  j = i - N4G - N4D; hi = g_Xh;  }
    else return;
    float4 v = ((const float4*)src)[j];
    __half h0 = __float2half_rn(v.x), h1 = __float2half_rn(v.y);
    __half h2 = __float2half_rn(v.z), h3 = __float2half_rn(v.w);
    uint32_t hp0 = (uint32_t)__half_as_ushort(h0) | ((uint32_t)__half_as_ushort(h1) << 16);
    uint32_t hp1 = (uint32_t)__half_as_ushort(h2) | ((uint32_t)__half_as_ushort(h3) << 16);
    ((uint2*)hi)[j] = make_uint2(hp0, hp1);
}

// ============================================================================
// GEMM1: 128 pairs x 64 I-cols (gate/up interleaved as 128 B-rows), K = 1024
// Single-pass fp16, ldmatrix frags, K-chunk 32, double buffer, 3 CTAs/SM.
// Fused silu(gate)*up epilogue -> g_Hh (fp16).
// ============================================================================
__global__ __launch_bounds__(256, 3) void gemm1_mma() {
    const int e     = blockIdx.z;
    const int start = g_offset[e];
    const int nrows = g_offset[e + 1] - start;
    const int row0  = blockIdx.y * 128;
    if (row0 >= nrows) return;
    const int col0 = blockIdx.x * 64;

    extern __shared__ char smem[];
    const uint32_t sbu = smem_to_u32(smem);
    const int tid  = threadIdx.x;
    const int wid  = tid >> 5, lane = tid & 31;
    const int g    = lane >> 2, tg = lane & 3;
    const int wm   = wid & 3, wn = wid >> 2;

    // loader: thread t owns row lr = t>>1, chunks lc, lc+1 (16B each) per matrix
    const int lr = tid >> 1;
    const int lc = (tid & 1) * 2;
    const bool v0 = (row0 + lr) < nrows;
    const int tok0 = v0 ? g_tok[start + row0 + lr] : 0;
    const __half* aptr = g_Xh + (size_t)tok0 * H_DIM;
    const size_t brow = ((size_t)e * 1024 + col0 + (lr >> 1) + (lr & 1) * 512) * H_DIM;
    uint32_t so[2];
    #pragma unroll
    for (int j = 0; j < 2; j++) so[j] = (uint32_t)(lr * 64 + (((lc + j) ^ (lr & 3)) << 4));

    // mma lane geometry (ldmatrix addressing)
    const int quad = lane >> 3, lr8 = lane & 7;
    const int a_r  = wm * 32 + (quad & 1) * 8 + lr8;   // + mt*16
    const int a_k8 = quad >> 1;
    const int b_rb = wn * 64 + (quad >> 1) * 8 + lr8;  // + ntp*16
    const int b_k8 = quad & 1;
    const uint32_t arx = (uint32_t)(a_r & 3);
    const uint32_t brx = (uint32_t)(b_rb & 3);
    uint32_t abase[2], bbase[4];
    #pragma unroll
    for (int mt = 0; mt < 2; mt++) abase[mt] = (uint32_t)((a_r + mt * 16) * 64);
    #pragma unroll
    for (int ntp = 0; ntp < 4; ntp++) bbase[ntp] = (uint32_t)((b_rb + ntp * 16) * 64);

    float acc[2][8][4];
    #pragma unroll
    for (int a = 0; a < 2; a++)
        #pragma unroll
        for (int b = 0; b < 8; b++)
            #pragma unroll
            for (int c = 0; c < 4; c++) acc[a][b][c] = 0.f;

    const int NCH = H_DIM / 32;   // 32
    {
        uint32_t s = sbu;
        #pragma unroll
        for (int j = 0; j < 2; j++) {
            const int eo = (lc + j) * 8;
            cp16(s + SA  + so[j], aptr + eo, v0 ? 16 : 0);
            cp16(s + SBH + so[j], g_GUh + brow + eo, 16);
        }
        CP_COMMIT();
    }

    #pragma unroll 1
    for (int ch = 0; ch < NCH; ch++) {
        if (ch + 1 < NCH) {
            const int kb = (ch + 1) * 32;
            uint32_t s = sbu + ((ch + 1) & 1) * G_ST;
            #pragma unroll
            for (int j = 0; j < 2; j++) {
                const int eo = kb + (lc + j) * 8;
                cp16(s + SA  + so[j], aptr + eo, v0 ? 16 : 0);
                cp16(s + SBH + so[j], g_GUh + brow + eo, 16);
            }
            CP_COMMIT();
            CP_WAIT1();
        } else {
            CP_WAIT0();
        }
        __syncthreads();
        const uint32_t st = sbu + (ch & 1) * G_ST;
        #pragma unroll
        for (int kh8 = 0; kh8 < 4; kh8 += 2) {
            uint32_t Ah[2][4];
            #pragma unroll
            for (int mt = 0; mt < 2; mt++)
                ldsm_x4(Ah[mt], st + SA + abase[mt] + ((((uint32_t)(kh8 + a_k8)) ^ arx) << 4));
            #pragma unroll
            for (int ntp = 0; ntp < 4; ntp++) {
                uint32_t Bh[4];
                ldsm_x4(Bh, st + SBH + bbase[ntp] + ((((uint32_t)(kh8 + b_k8)) ^ brx) << 4));
                #pragma unroll
                for (int mt = 0; mt < 2; mt++) {
                    mma16816(acc[mt][2 * ntp],     Ah[mt], Bh[0], Bh[1]);
                    mma16816(acc[mt][2 * ntp + 1], Ah[mt], Bh[2], Bh[3]);
                }
            }
        }
        __syncthreads();
    }

    // Epilogue: (c0,c1)=(gate,up) of one logical col; silu fuse; fp16 store.
    #pragma unroll
    for (int mt = 0; mt < 2; mt++) {
        #pragma unroll
        for (int nt = 0; nt < 8; nt++) {
            const int r  = wm * 32 + mt * 16 + g;
            const int jj = col0 + ((wn * 64 + nt * 8 + tg * 2) >> 1);
            const float* c = acc[mt][nt];
            #pragma unroll
            for (int hrow = 0; hrow < 2; hrow++) {
                const int rr = r + hrow * 8;
                if (row0 + rr < nrows) {
                    const float gate = c[hrow * 2], up = c[hrow * 2 + 1];
                    const float h = gate / (1.f + __expf(-gate)) * up;
                    g_Hh[(size_t)(start + row0 + rr) * I_DIM + jj] = __float2half_rn(h);
                }
            }
        }
    }
}

// ============================================================================
// GEMM2: 128 pairs x 128 H-cols, K = 512, single-pass fp16 -> g_pout (fp32)
// ============================================================================
__global__ __launch_bounds__(256, 3) void gemm2_mma() {
    const int e     = blockIdx.z;
    const int start = g_offset[e];
    const int nrows = g_offset[e + 1] - start;
    const int row0  = blockIdx.y * 128;
    if (row0 >= nrows) return;
    const int col0 = blockIdx.x * 128;

    extern __shared__ char smem[];
    const uint32_t sbu = smem_to_u32(smem);
    const int tid  = threadIdx.x;
    const int wid  = tid >> 5, lane = tid & 31;
    const int g    = lane >> 2, tg = lane & 3;
    const int wm   = wid & 3, wn = wid >> 2;

    const int lr = tid >> 1;
    const int lc = (tid & 1) * 2;
    const bool v0 = (row0 + lr) < nrows;
    const size_t arow = (size_t)(start + row0 + (v0 ? lr : 0)) * I_DIM;
    const size_t brow = ((size_t)e * H_DIM + col0 + lr) * I_DIM;
    uint32_t so[2];
    #pragma unroll
    for (int j = 0; j < 2; j++) so[j] = (uint32_t)(lr * 64 + (((lc + j) ^ (lr & 3)) << 4));

    const int quad = lane >> 3, lr8 = lane & 7;
    const int a_r  = wm * 32 + (quad & 1) * 8 + lr8;
    const int a_k8 = quad >> 1;
    const int b_rb = wn * 64 + (quad >> 1) * 8 + lr8;
    const int b_k8 = quad & 1;
    const uint32_t arx = (uint32_t)(a_r & 3);
    const uint32_t brx = (uint32_t)(b_rb & 3);
    uint32_t abase[2], bbase[4];
    #pragma unroll
    for (int mt = 0; mt < 2; mt++) abase[mt] = (uint32_t)((a_r + mt * 16) * 64);
    #pragma unroll
    for (int ntp = 0; ntp < 4; ntp++) bbase[ntp] = (uint32_t)((b_rb + ntp * 16) * 64);

    float acc[2][8][4];
    #pragma unroll
    for (int a = 0; a < 2; a++)
        #pragma unroll
        for (int b = 0; b < 8; b++)
            #pragma unroll
            for (int c = 0; c < 4; c++) acc[a][b][c] = 0.f;

    const int NCH = I_DIM / 32;   // 16
    {
        uint32_t s = sbu;
        #pragma unroll
        for (int j = 0; j < 2; j++) {
            const int eo = (lc + j) * 8;
            cp16(s + SA  + so[j], g_Hh + arow + eo, v0 ? 16 : 0);
            cp16(s + SBH + so[j], g_Dh + brow + eo, 16);
        }
        CP_COMMIT();
    }

    #pragma unroll 1
    for (int ch = 0; ch < NCH; ch++) {
        if (ch + 1 < NCH) {
            const int kb = (ch + 1) * 32;
            uint32_t s = sbu + ((ch + 1) & 1) * G_ST;
            #pragma unroll
            for (int j = 0; j < 2; j++) {
                const int eo = kb + (lc + j) * 8;
                cp16(s + SA  + so[j], g_Hh + arow + eo, v0 ? 16 : 0);
                cp16(s + SBH + so[j], g_Dh + brow + eo, 16);
            }
            CP_COMMIT();
            CP_WAIT1();
        } else {
            CP_WAIT0();
        }
        __syncthreads();
        const uint32_t st = sbu + (ch & 1) * G_ST;
        #pragma unroll
        for (int kh8 = 0; kh8 < 4; kh8 += 2) {
            uint32_t Ah[2][4];
            #pragma unroll
            for (int mt = 0; mt < 2; mt++)
                ldsm_x4(Ah[mt], st + SA + abase[mt] + ((((uint32_t)(kh8 + a_k8)) ^ arx) << 4));
            #pragma unroll
            for (int ntp = 0; ntp < 4; ntp++) {
                uint32_t Bh[4];
                ldsm_x4(Bh, st + SBH + bbase[ntp] + ((((uint32_t)(kh8 + b_k8)) ^ brx) << 4));
                #pragma unroll
                for (int mt = 0; mt < 2; mt++) {
                    mma16816(acc[mt][2 * ntp],     Ah[mt], Bh[0], Bh[1]);
                    mma16816(acc[mt][2 * ntp + 1], Ah[mt], Bh[2], Bh[3]);
                }
            }
        }
        __syncthreads();
    }

    #pragma unroll
    for (int mt = 0; mt < 2; mt++) {
        #pragma unroll
        for (int nt = 0; nt < 8; nt++) {
            const int r   = wm * 32 + mt * 16 + g;
            const int col = col0 + wn * 64 + nt * 8 + tg * 2;
            const float* c = acc[mt][nt];
            #pragma unroll
            for (int hrow = 0; hrow < 2; hrow++) {
                const int rr = r + hrow * 8;
                if (row0 + rr < nrows) {
                    float2 v = make_float2(c[hrow * 2], c[hrow * 2 + 1]);
                    *(float2*)(g_pout + (size_t)(start + row0 + rr) * H_DIM + col) = v;
                }
            }
        }
    }
}

// ============================================================================
// Reduce: out[t,h] = sum_k w[t,k] * g_pout[pos_of[t,k], h]  (deterministic)
// ============================================================================
__global__ void reduce_kernel(const float* __restrict__ wts, float* __restrict__ out) {
    const int i = blockIdx.x * blockDim.x + threadIdx.x;
    if (i >= T_TOK * H_DIM / 4) return;
    const int t  = i / (H_DIM / 4);
    const int h4 = (i % (H_DIM / 4)) * 4;
    float4 acc = make_float4(0.f, 0.f, 0.f, 0.f);
    #pragma unroll
    for (int k = 0; k < TOPK; k++) {
        const int   pos = g_pos_of[t * TOPK + k];
        const float w   = wts[t * TOPK + k];
        const float4 v  = *(const float4*)(g_pout + (size_t)pos * H_DIM + h4);
        acc.x = fmaf(w, v.x, acc.x);
        acc.y = fmaf(w, v.y, acc.y);
        acc.z = fmaf(w, v.z, acc.z);
        acc.w = fmaf(w, v.w, acc.w);
    }
    *(float4*)(out + (size_t)t * H_DIM + h4) = acc;
}

// ============================================================================
// Launch (graph-capturable: kernel launches only)
// ============================================================================
extern "C" void kernel_launch(void* const* d_in, const int* in_sizes, int n_in,
                              void* d_out, int out_size)
{
    const float* hidden  = (const float*)d_in[0];
    const int*   idx     = (const int*)  d_in[1];
    const float* wts     = (const float*)d_in[2];
    const float* gate_up = (const float*)d_in[3];
    const float* down    = (const float*)d_in[4];
    float*       out     = (float*)d_out;

    routing_kernel<<<1, 256>>>(idx);

    const int n4all = N4G + N4D + N4X;
    split_all_kernel<<<(n4all + 255) / 256, 256>>>(gate_up, down, hidden);

    dim3 g1(I_DIM / 64, NPAIR / 128, N_EXP);
    gemm1_mma<<<g1, 256, G_TOTAL>>>();

    dim3 g2(H_DIM / 128, NPAIR / 128, N_EXP);
    gemm2_mma<<<g2, 256, G_TOTAL>>>();

    reduce_kernel<<<(T_TOK * H_DIM / 4 + 255) / 256, 256>>>(wts, out);
}

// round 10
// speedup vs baseline: 1.0125x; 1.0125x over previous
#include <cuda_runtime.h>
#include <cuda_fp16.h>
#include <cstdint>
#include <math.h>

// Problem constants
#define T_TOK 1024
#define H_DIM 1024
#define I_DIM 512
#define N_EXP 16
#define TOPK  4
#define NPAIR (T_TOK * TOPK)   // 4096

// ============================================================================
// Scratch (__device__ globals; allocations are forbidden)
// ============================================================================
__device__ int   g_offset[N_EXP + 1];
__device__ int   g_tok[NPAIR];
__device__ float g_wt[NPAIR];

__device__ __half g_Xh[T_TOK * H_DIM];               // hidden, fp16
__device__ __half g_GUh[N_EXP * 2 * I_DIM * H_DIM];  // gate_up, fp16
__device__ __half g_Dh[N_EXP * H_DIM * I_DIM];       // down, fp16
__device__ __half g_Hh[NPAIR * I_DIM];               // silu(g)*u, fp16

// ============================================================================
// PTX helpers (sm_80-era: cp.async, ldmatrix, mma.sync — legal on compute_103)
// ============================================================================
__device__ __forceinline__ uint32_t smem_to_u32(const void* p) {
    uint32_t a;
    asm("{ .reg .u64 t; cvta.to.shared.u64 t, %1; cvt.u32.u64 %0, t; }" : "=r"(a) : "l"(p));
    return a;
}
__device__ __forceinline__ void cp16(uint32_t saddr, const void* g, int szbytes) {
    asm volatile("cp.async.cg.shared.global [%0], [%1], 16, %2;"
                 :: "r"(saddr), "l"(g), "r"(szbytes) : "memory");
}
#define CP_COMMIT() asm volatile("cp.async.commit_group;" ::: "memory")
#define CP_WAIT1()  asm volatile("cp.async.wait_group 1;" ::: "memory")

__device__ __forceinline__ void ldsm_x4(uint32_t* r, uint32_t addr) {
    asm volatile("ldmatrix.sync.aligned.m8n8.x4.shared.b16 {%0,%1,%2,%3}, [%4];"
                 : "=r"(r[0]), "=r"(r[1]), "=r"(r[2]), "=r"(r[3]) : "r"(addr));
}
__device__ __forceinline__ void mma16816(float* c, const uint32_t* a, uint32_t b0, uint32_t b1) {
    asm volatile(
        "mma.sync.aligned.m16n8k16.row.col.f32.f16.f16.f32 "
        "{%0,%1,%2,%3}, {%4,%5,%6,%7}, {%8,%9}, {%0,%1,%2,%3};"
        : "+f"(c[0]), "+f"(c[1]), "+f"(c[2]), "+f"(c[3])
        : "r"(a[0]), "r"(a[1]), "r"(a[2]), "r"(a[3]), "r"(b0), "r"(b1));
}

// Tile smem: [128 rows][32 fp16] = 64B/row, 4x 16B chunks/row, chunk' = chunk ^ (row&3)
// Stage: A | B (2 x 8KB = 16KB); 3-stage ring = 48KB (both GEMMs)
#define SA    0
#define SBH   8192
#define G_ST  16384
#define G_TOTAL (3 * G_ST)   // 49152 = 48KB (within default dynamic smem limit)

// ============================================================================
// Prep kernel (1 launch): fp32->fp16 converts + d_out zeroing + routing block
// ============================================================================
#define N4G (N_EXP * 2 * I_DIM * H_DIM / 4)   // 4194304
#define N4D (N_EXP * H_DIM * I_DIM / 4)       // 2097152
#define N4X (T_TOK * H_DIM / 4)               // 262144
#define N4O (T_TOK * H_DIM / 4)               // 262144 (output zeroing, float4)
#define PREP_BLOCKS ((N4G + N4D + N4X + N4O) / 256)   // 26624

__global__ void prep_kernel(const float* __restrict__ gu,
                            const float* __restrict__ dn,
                            const float* __restrict__ x,
                            const int*   __restrict__ idx,
                            const float* __restrict__ wts,
                            float*       __restrict__ out) {
    const int b = blockIdx.x;
    const int tid = threadIdx.x;

    if (b == PREP_BLOCKS) {
        // Routing: count -> prefix -> scatter (records token and weight per slot)
        __shared__ int cnt[N_EXP];
        __shared__ int off[N_EXP];
        if (tid < N_EXP) cnt[tid] = 0;
        __syncthreads();
        #pragma unroll
        for (int j = 0; j < NPAIR / 256; j++)
            atomicAdd(&cnt[idx[tid + j * 256]], 1);
        __syncthreads();
        if (tid == 0) {
            int acc = 0;
            for (int e = 0; e < N_EXP; e++) { off[e] = acc; g_offset[e] = acc; acc += cnt[e]; }
            g_offset[N_EXP] = acc;
        }
        __syncthreads();
        if (tid < N_EXP) cnt[tid] = 0;
        __syncthreads();
        #pragma unroll
        for (int j = 0; j < NPAIR / 256; j++) {
            const int i = tid + j * 256;
            const int e = idx[i];
            const int pos = off[e] + atomicAdd(&cnt[e], 1);
            g_tok[pos] = i >> 2;
            g_wt[pos]  = wts[i];
        }
        return;
    }

    const int i = b * 256 + tid;
    if (i < N4G + N4D + N4X) {
        const float* src;
        __half* hi;
        int j;
        if (i < N4G)            { src = gu; j = i;             hi = g_GUh; }
        else if (i < N4G + N4D) { src = dn; j = i - N4G;       hi = g_Dh;  }
        else                    { src = x;  j = i - N4G - N4D; hi = g_Xh;  }
        float4 v = ((const float4*)src)[j];
        __half h0 = __float2half_rn(v.x), h1 = __float2half_rn(v.y);
        __half h2 = __float2half_rn(v.z), h3 = __float2half_rn(v.w);
        uint32_t hp0 = (uint32_t)__half_as_ushort(h0) | ((uint32_t)__half_as_ushort(h1) << 16);
        uint32_t hp1 = (uint32_t)__half_as_ushort(h2) | ((uint32_t)__half_as_ushort(h3) << 16);
        ((uint2*)hi)[j] = make_uint2(hp0, hp1);
    } else {
        const int j = i - (N4G + N4D + N4X);
        ((float4*)out)[j] = make_float4(0.f, 0.f, 0.f, 0.f);
    }
}

// ============================================================================
// GEMM1: 128 pairs x 64 I-cols (gate/up interleaved as 128 B-rows), K = 1024
// Single-pass fp16, ldmatrix, 3-stage cp.async ring, one sync per chunk.
// Fused silu(gate)*up epilogue -> g_Hh (fp16).
// ============================================================================
__global__ __launch_bounds__(256, 3) void gemm1_mma() {
    const int e     = blockIdx.z;
    const int start = g_offset[e];
    const int nrows = g_offset[e + 1] - start;
    const int row0  = blockIdx.y * 128;
    if (row0 >= nrows) return;
    const int col0 = blockIdx.x * 64;

    extern __shared__ char smem[];
    const uint32_t sbu = smem_to_u32(smem);
    const int tid  = threadIdx.x;
    const int wid  = tid >> 5, lane = tid & 31;
    const int g    = lane >> 2, tg = lane & 3;
    const int wm   = wid & 3, wn = wid >> 2;

    // loader: thread t owns row lr = t>>1, chunks lc, lc+1 (16B each) per matrix
    const int lr = tid >> 1;
    const int lc = (tid & 1) * 2;
    const bool v0 = (row0 + lr) < nrows;
    const int tok0 = v0 ? g_tok[start + row0 + lr] : 0;
    const __half* aptr = g_Xh + (size_t)tok0 * H_DIM;
    const size_t brow = ((size_t)e * 1024 + col0 + (lr >> 1) + (lr & 1) * 512) * H_DIM;
    uint32_t so[2];
    #pragma unroll
    for (int j = 0; j < 2; j++) so[j] = (uint32_t)(lr * 64 + (((lc + j) ^ (lr & 3)) << 4));

    // mma lane geometry (ldmatrix addressing)
    const int quad = lane >> 3, lr8 = lane & 7;
    const int a_r  = wm * 32 + (quad & 1) * 8 + lr8;   // + mt*16
    const int a_k8 = quad >> 1;
    const int b_rb = wn * 64 + (quad >> 1) * 8 + lr8;  // + ntp*16
    const int b_k8 = quad & 1;
    const uint32_t arx = (uint32_t)(a_r & 3);
    const uint32_t brx = (uint32_t)(b_rb & 3);
    uint32_t abase[2], bbase[4];
    #pragma unroll
    for (int mt = 0; mt < 2; mt++) abase[mt] = (uint32_t)((a_r + mt * 16) * 64);
    #pragma unroll
    for (int ntp = 0; ntp < 4; ntp++) bbase[ntp] = (uint32_t)((b_rb + ntp * 16) * 64);

    float acc[2][8][4];
    #pragma unroll
    for (int a = 0; a < 2; a++)
        #pragma unroll
        for (int b = 0; b < 8; b++)
            #pragma unroll
            for (int c = 0; c < 4; c++) acc[a][b][c] = 0.f;

    const int NCH = H_DIM / 32;   // 32
    // prologue: issue stages 0 and 1
    #pragma unroll
    for (int s = 0; s < 2; s++) {
        uint32_t sb = sbu + s * G_ST;
        #pragma unroll
        for (int j = 0; j < 2; j++) {
            const int eo = s * 32 + (lc + j) * 8;
            cp16(sb + SA  + so[j], aptr + eo, v0 ? 16 : 0);
            cp16(sb + SBH + so[j], g_GUh + brow + eo, 16);
        }
        CP_COMMIT();
    }

    int cslot = 0, nslot = 2;
    #pragma unroll 1
    for (int ch = 0; ch < NCH; ch++) {
        CP_WAIT1();
        __syncthreads();
        {
            const int nc = ch + 2;
            if (nc < NCH) {
                uint32_t sb = sbu + nslot * G_ST;
                #pragma unroll
                for (int j = 0; j < 2; j++) {
                    const int eo = nc * 32 + (lc + j) * 8;
                    cp16(sb + SA  + so[j], aptr + eo, v0 ? 16 : 0);
                    cp16(sb + SBH + so[j], g_GUh + brow + eo, 16);
                }
            }
            CP_COMMIT();
        }
        const uint32_t st = sbu + cslot * G_ST;
        #pragma unroll
        for (int kh8 = 0; kh8 < 4; kh8 += 2) {
            uint32_t Ah[2][4];
            #pragma unroll
            for (int mt = 0; mt < 2; mt++)
                ldsm_x4(Ah[mt], st + SA + abase[mt] + ((((uint32_t)(kh8 + a_k8)) ^ arx) << 4));
            #pragma unroll
            for (int ntp = 0; ntp < 4; ntp++) {
                uint32_t Bh[4];
                ldsm_x4(Bh, st + SBH + bbase[ntp] + ((((uint32_t)(kh8 + b_k8)) ^ brx) << 4));
                #pragma unroll
                for (int mt = 0; mt < 2; mt++) {
                    mma16816(acc[mt][2 * ntp],     Ah[mt], Bh[0], Bh[1]);
                    mma16816(acc[mt][2 * ntp + 1], Ah[mt], Bh[2], Bh[3]);
                }
            }
        }
        cslot = (cslot == 2) ? 0 : cslot + 1;
        nslot = (nslot == 2) ? 0 : nslot + 1;
    }

    // Epilogue: (c0,c1)=(gate,up) of one logical col; silu fuse; fp16 store.
    #pragma unroll
    for (int mt = 0; mt < 2; mt++) {
        #pragma unroll
        for (int nt = 0; nt < 8; nt++) {
            const int r  = wm * 32 + mt * 16 + g;
            const int jj = col0 + ((wn * 64 + nt * 8 + tg * 2) >> 1);
            const float* c = acc[mt][nt];
            #pragma unroll
            for (int hrow = 0; hrow < 2; hrow++) {
                const int rr = r + hrow * 8;
                if (row0 + rr < nrows) {
                    const float gate = c[hrow * 2], up = c[hrow * 2 + 1];
                    const float h = gate / (1.f + __expf(-gate)) * up;
                    g_Hh[(size_t)(start + row0 + rr) * I_DIM + jj] = __float2half_rn(h);
                }
            }
        }
    }
}

// ============================================================================
// GEMM2: 128 pairs x 128 H-cols, K = 512, single-pass fp16, 3-stage ring.
// Epilogue: atomicAdd(out[t,h], w * acc) — reduce kernel eliminated.
// ============================================================================
__global__ __launch_bounds__(256, 3) void gemm2_mma(float* __restrict__ out) {
    const int e     = blockIdx.z;
    const int start = g_offset[e];
    const int nrows = g_offset[e + 1] - start;
    const int row0  = blockIdx.y * 128;
    if (row0 >= nrows) return;
    const int col0 = blockIdx.x * 128;

    extern __shared__ char smem[];
    const uint32_t sbu = smem_to_u32(smem);
    const int tid  = threadIdx.x;
    const int wid  = tid >> 5, lane = tid & 31;
    const int g    = lane >> 2, tg = lane & 3;
    const int wm   = wid & 3, wn = wid >> 2;

    const int lr = tid >> 1;
    const int lc = (tid & 1) * 2;
    const bool v0 = (row0 + lr) < nrows;
    const size_t arow = (size_t)(start + row0 + (v0 ? lr : 0)) * I_DIM;
    const size_t brow = ((size_t)e * H_DIM + col0 + lr) * I_DIM;
    uint32_t so[2];
    #pragma unroll
    for (int j = 0; j < 2; j++) so[j] = (uint32_t)(lr * 64 + (((lc + j) ^ (lr & 3)) << 4));

    const int quad = lane >> 3, lr8 = lane & 7;
    const int a_r  = wm * 32 + (quad & 1) * 8 + lr8;
    const int a_k8 = quad >> 1;
    const int b_rb = wn * 64 + (quad >> 1) * 8 + lr8;
    const int b_k8 = quad & 1;
    const uint32_t arx = (uint32_t)(a_r & 3);
    const uint32_t brx = (uint32_t)(b_rb & 3);
    uint32_t abase[2], bbase[4];
    #pragma unroll
    for (int mt = 0; mt < 2; mt++) abase[mt] = (uint32_t)((a_r + mt * 16) * 64);
    #pragma unroll
    for (int ntp = 0; ntp < 4; ntp++) bbase[ntp] = (uint32_t)((b_rb + ntp * 16) * 64);

    float acc[2][8][4];
    #pragma unroll
    for (int a = 0; a < 2; a++)
        #pragma unroll
        for (int b = 0; b < 8; b++)
            #pragma unroll
            for (int c = 0; c < 4; c++) acc[a][b][c] = 0.f;

    const int NCH = I_DIM / 32;   // 16
    #pragma unroll
    for (int s = 0; s < 2; s++) {
        uint32_t sb = sbu + s * G_ST;
        #pragma unroll
        for (int j = 0; j < 2; j++) {
            const int eo = s * 32 + (lc + j) * 8;
            cp16(sb + SA  + so[j], g_Hh + arow + eo, v0 ? 16 : 0);
            cp16(sb + SBH + so[j], g_Dh + brow + eo, 16);
        }
        CP_COMMIT();
    }

    int cslot = 0, nslot = 2;
    #pragma unroll 1
    for (int ch = 0; ch < NCH; ch++) {
        CP_WAIT1();
        __syncthreads();
        {
            const int nc = ch + 2;
            if (nc < NCH) {
                uint32_t sb = sbu + nslot * G_ST;
                #pragma unroll
                for (int j = 0; j < 2; j++) {
                    const int eo = nc * 32 + (lc + j) * 8;
                    cp16(sb + SA  + so[j], g_Hh + arow + eo, v0 ? 16 : 0);
                    cp16(sb + SBH + so[j], g_Dh + brow + eo, 16);
                }
            }
            CP_COMMIT();
        }
        const uint32_t st = sbu + cslot * G_ST;
        #pragma unroll
        for (int kh8 = 0; kh8 < 4; kh8 += 2) {
            uint32_t Ah[2][4];
            #pragma unroll
            for (int mt = 0; mt < 2; mt++)
                ldsm_x4(Ah[mt], st + SA + abase[mt] + ((((uint32_t)(kh8 + a_k8)) ^ arx) << 4));
            #pragma unroll
            for (int ntp = 0; ntp < 4; ntp++) {
                uint32_t Bh[4];
                ldsm_x4(Bh, st + SBH + bbase[ntp] + ((((uint32_t)(kh8 + b_k8)) ^ brx) << 4));
                #pragma unroll
                for (int mt = 0; mt < 2; mt++) {
                    mma16816(acc[mt][2 * ntp],     Ah[mt], Bh[0], Bh[1]);
                    mma16816(acc[mt][2 * ntp + 1], Ah[mt], Bh[2], Bh[3]);
                }
            }
        }
        cslot = (cslot == 2) ? 0 : cslot + 1;
        nslot = (nslot == 2) ? 0 : nslot + 1;
    }

    // Epilogue: weighted atomic accumulate into out[t, :]
    #pragma unroll
    for (int mt = 0; mt < 2; mt++) {
        #pragma unroll
        for (int hrow = 0; hrow < 2; hrow++) {
            const int rr = wm * 32 + mt * 16 + g + hrow * 8;
            if (row0 + rr < nrows) {
                const int pos = start + row0 + rr;
                const int t   = g_tok[pos];
                const float w = g_wt[pos];
                float* orow = out + (size_t)t * H_DIM;
                #pragma unroll
                for (int nt = 0; nt < 8; nt++) {
                    const int col = col0 + wn * 64 + nt * 8 + tg * 2;
                    atomicAdd(orow + col,     w * acc[mt][nt][hrow * 2]);
                    atomicAdd(orow + col + 1, w * acc[mt][nt][hrow * 2 + 1]);
                }
            }
        }
    }
}

// ============================================================================
// Launch (graph-capturable: kernel launches only, 3 launches)
// ============================================================================
extern "C" void kernel_launch(void* const* d_in, const int* in_sizes, int n_in,
                              void* d_out, int out_size)
{
    const float* hidden  = (const float*)d_in[0];
    const int*   idx     = (const int*)  d_in[1];
    const float* wts     = (const float*)d_in[2];
    const float* gate_up = (const float*)d_in[3];
    const float* down    = (const float*)d_in[4];
    float*       out     = (float*)d_out;

    prep_kernel<<<PREP_BLOCKS + 1, 256>>>(gate_up, down, hidden, idx, wts, out);

    dim3 g1(I_DIM / 64, NPAIR / 128, N_EXP);
    gemm1_mma<<<g1, 256, G_TOTAL>>>();

    dim3 g2(H_DIM / 128, NPAIR / 128, N_EXP);
    gemm2_mma<<<g2, 256, G_TOTAL>>>(out);
}

// round 11
// speedup vs baseline: 1.1862x; 1.1716x over previous
#include <cuda_runtime.h>
#include <cuda_fp16.h>
#include <cstdint>
#include <math.h>

// Problem constants
#define T_TOK 1024
#define H_DIM 1024
#define I_DIM 512
#define N_EXP 16
#define TOPK  4
#define NPAIR (T_TOK * TOPK)   // 4096

// ============================================================================
// Scratch (__device__ globals; allocations are forbidden)
// ============================================================================
__device__ int   g_offset[N_EXP + 1];
__device__ int   g_tok[NPAIR];
__device__ float g_wt[NPAIR];

__device__ __half g_Xh[T_TOK * H_DIM];               // hidden, fp16
__device__ __half g_GUh[N_EXP * 2 * I_DIM * H_DIM];  // gate_up, fp16
__device__ __half g_Dh[N_EXP * H_DIM * I_DIM];       // down, fp16
__device__ __half g_Hh[NPAIR * I_DIM];               // silu(g)*u, fp16

// ============================================================================
// PTX helpers (sm_80-era: cp.async, ldmatrix, mma.sync — legal on compute_103)
// ============================================================================
__device__ __forceinline__ uint32_t smem_to_u32(const void* p) {
    uint32_t a;
    asm("{ .reg .u64 t; cvta.to.shared.u64 t, %1; cvt.u32.u64 %0, t; }" : "=r"(a) : "l"(p));
    return a;
}
__device__ __forceinline__ void cp16(uint32_t saddr, const void* g, int szbytes) {
    asm volatile("cp.async.cg.shared.global [%0], [%1], 16, %2;"
                 :: "r"(saddr), "l"(g), "r"(szbytes) : "memory");
}
#define CP_COMMIT() asm volatile("cp.async.commit_group;" ::: "memory")
#define CP_WAIT1()  asm volatile("cp.async.wait_group 1;" ::: "memory")

__device__ __forceinline__ void ldsm_x4(uint32_t* r, uint32_t addr) {
    asm volatile("ldmatrix.sync.aligned.m8n8.x4.shared.b16 {%0,%1,%2,%3}, [%4];"
                 : "=r"(r[0]), "=r"(r[1]), "=r"(r[2]), "=r"(r[3]) : "r"(addr));
}
__device__ __forceinline__ void mma16816(float* c, const uint32_t* a, uint32_t b0, uint32_t b1) {
    asm volatile(
        "mma.sync.aligned.m16n8k16.row.col.f32.f16.f16.f32 "
        "{%0,%1,%2,%3}, {%4,%5,%6,%7}, {%8,%9}, {%0,%1,%2,%3};"
        : "+f"(c[0]), "+f"(c[1]), "+f"(c[2]), "+f"(c[3])
        : "r"(a[0]), "r"(a[1]), "r"(a[2]), "r"(a[3]), "r"(b0), "r"(b1));
}

// Tile smem rows are 64B (32 fp16), 4x16B chunks, chunk' = chunk ^ (row&3)
// GEMM1 stage: A 128x32 (8KB) | B 64x32 (4KB)  = 12KB; 3-stage ring = 36KB
// GEMM2 stage: A 128x32 (8KB) | B 128x32 (8KB) = 16KB; 3-stage ring = 48KB
#define G1_SA 0
#define G1_SB 8192
#define G1_ST 12288
#define G1_TOTAL (3 * G1_ST)
#define G2_SA 0
#define G2_SB 8192
#define G2_ST 16384
#define G2_TOTAL (3 * G2_ST)

// ============================================================================
// Prep kernel (1 launch): fp32->fp16 converts + d_out zeroing + routing block
// Each thread handles 2 consecutive float4s (regions are all even-sized).
// ============================================================================
#define N4G (N_EXP * 2 * I_DIM * H_DIM / 4)   // 4194304
#define N4D (N_EXP * H_DIM * I_DIM / 4)       // 2097152
#define N4X (T_TOK * H_DIM / 4)               // 262144
#define N4O (T_TOK * H_DIM / 4)               // 262144
#define PREP_BLOCKS ((N4G + N4D + N4X + N4O) / 512)   // 13312

__global__ void prep_kernel(const float* __restrict__ gu,
                            const float* __restrict__ dn,
                            const float* __restrict__ x,
                            const int*   __restrict__ idx,
                            const float* __restrict__ wts,
                            float*       __restrict__ out) {
    const int b = blockIdx.x;
    const int tid = threadIdx.x;

    if (b == PREP_BLOCKS) {
        __shared__ int cnt[N_EXP];
        __shared__ int off[N_EXP];
        if (tid < N_EXP) cnt[tid] = 0;
        __syncthreads();
        #pragma unroll
        for (int j = 0; j < NPAIR / 256; j++)
            atomicAdd(&cnt[idx[tid + j * 256]], 1);
        __syncthreads();
        if (tid == 0) {
            int acc = 0;
            for (int e = 0; e < N_EXP; e++) { off[e] = acc; g_offset[e] = acc; acc += cnt[e]; }
            g_offset[N_EXP] = acc;
        }
        __syncthreads();
        if (tid < N_EXP) cnt[tid] = 0;
        __syncthreads();
        #pragma unroll
        for (int j = 0; j < NPAIR / 256; j++) {
            const int i = tid + j * 256;
            const int e = idx[i];
            const int pos = off[e] + atomicAdd(&cnt[e], 1);
            g_tok[pos] = i >> 2;
            g_wt[pos]  = wts[i];
        }
        return;
    }

    const int i = (b * 256 + tid) * 2;    // first float4 index (even)
    if (i < N4G + N4D + N4X) {
        const float* src;
        __half* hi;
        int j;
        if (i < N4G)            { src = gu; j = i;             hi = g_GUh; }
        else if (i < N4G + N4D) { src = dn; j = i - N4G;       hi = g_Dh;  }
        else                    { src = x;  j = i - N4G - N4D; hi = g_Xh;  }
        #pragma unroll
        for (int q = 0; q < 2; q++) {
            float4 v = ((const float4*)src)[j + q];
            __half h0 = __float2half_rn(v.x), h1 = __float2half_rn(v.y);
            __half h2 = __float2half_rn(v.z), h3 = __float2half_rn(v.w);
            uint32_t hp0 = (uint32_t)__half_as_ushort(h0) | ((uint32_t)__half_as_ushort(h1) << 16);
            uint32_t hp1 = (uint32_t)__half_as_ushort(h2) | ((uint32_t)__half_as_ushort(h3) << 16);
            ((uint2*)hi)[j + q] = make_uint2(hp0, hp1);
        }
    } else {
        const int j = i - (N4G + N4D + N4X);
        ((float4*)out)[j]     = make_float4(0.f, 0.f, 0.f, 0.f);
        ((float4*)out)[j + 1] = make_float4(0.f, 0.f, 0.f, 0.f);
    }
}

// ============================================================================
// GEMM1: 128 pairs x 32 I-cols (gate/up interleaved as 64 B-rows), K = 1024
// Single-pass fp16, ldmatrix, 3-stage ring. 16 col-tiles -> 2x live CTAs.
// Fused silu(gate)*up epilogue -> g_Hh (fp16).
// ============================================================================
__global__ __launch_bounds__(256, 3) void gemm1_mma() {
    const int e     = blockIdx.z;
    const int start = g_offset[e];
    const int nrows = g_offset[e + 1] - start;
    const int row0  = blockIdx.y * 128;
    if (row0 >= nrows) return;
    const int col0 = blockIdx.x * 32;          // logical I columns (32 per CTA)

    extern __shared__ char smem[];
    const uint32_t sbu = smem_to_u32(smem);
    const int tid  = threadIdx.x;
    const int wid  = tid >> 5, lane = tid & 31;
    const int g    = lane >> 2, tg = lane & 3;
    const int wm   = wid & 3, wn = wid >> 2;   // 4 warps M x 2 warps N(32 B-rows)

    // A loader: thread t owns row lr = t>>1, chunks lc, lc+1
    const int lr = tid >> 1;
    const int lc = (tid & 1) * 2;
    const bool v0 = (row0 + lr) < nrows;
    const int tok0 = v0 ? g_tok[start + row0 + lr] : 0;
    const __half* aptr = g_Xh + (size_t)tok0 * H_DIM;
    uint32_t soA[2];
    #pragma unroll
    for (int j = 0; j < 2; j++) soA[j] = (uint32_t)(lr * 64 + (((lc + j) ^ (lr & 3)) << 4));

    // B loader: thread t owns row nb = t>>2 (0..63), chunk cb = t&3
    const int nb = tid >> 2, cb = tid & 3;
    const size_t brow = ((size_t)e * 1024 + col0 + (nb >> 1) + (nb & 1) * 512) * H_DIM;
    const uint32_t soB = (uint32_t)(nb * 64 + ((cb ^ (nb & 3)) << 4));

    // mma lane geometry (ldmatrix addressing)
    const int quad = lane >> 3, lr8 = lane & 7;
    const int a_r  = wm * 32 + (quad & 1) * 8 + lr8;   // + mt*16
    const int a_k8 = quad >> 1;
    const int b_rb = wn * 32 + (quad >> 1) * 8 + lr8;  // + ntp*16
    const int b_k8 = quad & 1;
    const uint32_t arx = (uint32_t)(a_r & 3);
    const uint32_t brx = (uint32_t)(b_rb & 3);
    uint32_t abase[2], bbase[2];
    #pragma unroll
    for (int mt = 0; mt < 2; mt++) abase[mt] = (uint32_t)((a_r + mt * 16) * 64);
    #pragma unroll
    for (int ntp = 0; ntp < 2; ntp++) bbase[ntp] = (uint32_t)((b_rb + ntp * 16) * 64);

    float acc[2][4][4];
    #pragma unroll
    for (int a = 0; a < 2; a++)
        #pragma unroll
        for (int b = 0; b < 4; b++)
            #pragma unroll
            for (int c = 0; c < 4; c++) acc[a][b][c] = 0.f;

    const int NCH = H_DIM / 32;   // 32
    #pragma unroll
    for (int s = 0; s < 2; s++) {
        uint32_t sb = sbu + s * G1_ST;
        #pragma unroll
        for (int j = 0; j < 2; j++)
            cp16(sb + G1_SA + soA[j], aptr + s * 32 + (lc + j) * 8, v0 ? 16 : 0);
        cp16(sb + G1_SB + soB, g_GUh + brow + s * 32 + cb * 8, 16);
        CP_COMMIT();
    }

    int cslot = 0, nslot = 2;
    #pragma unroll 1
    for (int ch = 0; ch < NCH; ch++) {
        CP_WAIT1();
        __syncthreads();
        {
            const int nc = ch + 2;
            if (nc < NCH) {
                uint32_t sb = sbu + nslot * G1_ST;
                #pragma unroll
                for (int j = 0; j < 2; j++)
                    cp16(sb + G1_SA + soA[j], aptr + nc * 32 + (lc + j) * 8, v0 ? 16 : 0);
                cp16(sb + G1_SB + soB, g_GUh + brow + nc * 32 + cb * 8, 16);
            }
            CP_COMMIT();
        }
        const uint32_t st = sbu + cslot * G1_ST;
        #pragma unroll
        for (int kh8 = 0; kh8 < 4; kh8 += 2) {
            uint32_t Ah[2][4];
            #pragma unroll
            for (int mt = 0; mt < 2; mt++)
                ldsm_x4(Ah[mt], st + G1_SA + abase[mt] + ((((uint32_t)(kh8 + a_k8)) ^ arx) << 4));
            #pragma unroll
            for (int ntp = 0; ntp < 2; ntp++) {
                uint32_t Bh[4];
                ldsm_x4(Bh, st + G1_SB + bbase[ntp] + ((((uint32_t)(kh8 + b_k8)) ^ brx) << 4));
                #pragma unroll
                for (int mt = 0; mt < 2; mt++) {
                    mma16816(acc[mt][2 * ntp],     Ah[mt], Bh[0], Bh[1]);
                    mma16816(acc[mt][2 * ntp + 1], Ah[mt], Bh[2], Bh[3]);
                }
            }
        }
        cslot = (cslot == 2) ? 0 : cslot + 1;
        nslot = (nslot == 2) ? 0 : nslot + 1;
    }

    // Epilogue: (c0,c1)=(gate,up) of one logical col; silu fuse; fp16 store.
    #pragma unroll
    for (int mt = 0; mt < 2; mt++) {
        #pragma unroll
        for (int nt = 0; nt < 4; nt++) {
            const int r  = wm * 32 + mt * 16 + g;
            const int jj = col0 + ((wn * 32 + nt * 8 + tg * 2) >> 1);
            const float* c = acc[mt][nt];
            #pragma unroll
            for (int hrow = 0; hrow < 2; hrow++) {
                const int rr = r + hrow * 8;
                if (row0 + rr < nrows) {
                    const float gate = c[hrow * 2], up = c[hrow * 2 + 1];
                    const float h = gate / (1.f + __expf(-gate)) * up;
                    g_Hh[(size_t)(start + row0 + rr) * I_DIM + jj] = __float2half_rn(h);
                }
            }
        }
    }
}

// ============================================================================
// GEMM2: 128 pairs x 128 H-cols, split-K x2 (256 each), single-pass fp16.
// Epilogue: atomicAdd(out[t,h], w * partial) — partial-K sums compose.
// ============================================================================
__global__ __launch_bounds__(256, 3) void gemm2_mma(float* __restrict__ out) {
    const int e     = blockIdx.z >> 1;
    const int ks    = blockIdx.z & 1;
    const int start = g_offset[e];
    const int nrows = g_offset[e + 1] - start;
    const int row0  = blockIdx.y * 128;
    if (row0 >= nrows) return;
    const int col0 = blockIdx.x * 128;
    const int kofs = ks * 256;                 // K half for this CTA

    extern __shared__ char smem[];
    const uint32_t sbu = smem_to_u32(smem);
    const int tid  = threadIdx.x;
    const int wid  = tid >> 5, lane = tid & 31;
    const int g    = lane >> 2, tg = lane & 3;
    const int wm   = wid & 3, wn = wid >> 2;

    const int lr = tid >> 1;
    const int lc = (tid & 1) * 2;
    const bool v0 = (row0 + lr) < nrows;
    const size_t arow = (size_t)(start + row0 + (v0 ? lr : 0)) * I_DIM;
    const size_t brow = ((size_t)e * H_DIM + col0 + lr) * I_DIM;
    uint32_t so[2];
    #pragma unroll
    for (int j = 0; j < 2; j++) so[j] = (uint32_t)(lr * 64 + (((lc + j) ^ (lr & 3)) << 4));

    const int quad = lane >> 3, lr8 = lane & 7;
    const int a_r  = wm * 32 + (quad & 1) * 8 + lr8;
    const int a_k8 = quad >> 1;
    const int b_rb = wn * 64 + (quad >> 1) * 8 + lr8;
    const int b_k8 = quad & 1;
    const uint32_t arx = (uint32_t)(a_r & 3);
    const uint32_t brx = (uint32_t)(b_rb & 3);
    uint32_t abase[2], bbase[4];
    #pragma unroll
    for (int mt = 0; mt < 2; mt++) abase[mt] = (uint32_t)((a_r + mt * 16) * 64);
    #pragma unroll
    for (int ntp = 0; ntp < 4; ntp++) bbase[ntp] = (uint32_t)((b_rb + ntp * 16) * 64);

    float acc[2][8][4];
    #pragma unroll
    for (int a = 0; a < 2; a++)
        #pragma unroll
        for (int b = 0; b < 8; b++)
            #pragma unroll
            for (int c = 0; c < 4; c++) acc[a][b][c] = 0.f;

    const int NCH = 256 / 32;   // 8 chunks in this K half
    #pragma unroll
    for (int s = 0; s < 2; s++) {
        uint32_t sb = sbu + s * G2_ST;
        #pragma unroll
        for (int j = 0; j < 2; j++) {
            const int eo = kofs + s * 32 + (lc + j) * 8;
            cp16(sb + G2_SA + so[j], g_Hh + arow + eo, v0 ? 16 : 0);
            cp16(sb + G2_SB + so[j], g_Dh + brow + eo, 16);
        }
        CP_COMMIT();
    }

    int cslot = 0, nslot = 2;
    #pragma unroll 1
    for (int ch = 0; ch < NCH; ch++) {
        CP_WAIT1();
        __syncthreads();
        {
            const int nc = ch + 2;
            if (nc < NCH) {
                uint32_t sb = sbu + nslot * G2_ST;
                #pragma unroll
                for (int j = 0; j < 2; j++) {
                    const int eo = kofs + nc * 32 + (lc + j) * 8;
                    cp16(sb + G2_SA + so[j], g_Hh + arow + eo, v0 ? 16 : 0);
                    cp16(sb + G2_SB + so[j], g_Dh + brow + eo, 16);
                }
            }
            CP_COMMIT();
        }
        const uint32_t st = sbu + cslot * G2_ST;
        #pragma unroll
        for (int kh8 = 0; kh8 < 4; kh8 += 2) {
            uint32_t Ah[2][4];
            #pragma unroll
            for (int mt = 0; mt < 2; mt++)
                ldsm_x4(Ah[mt], st + G2_SA + abase[mt] + ((((uint32_t)(kh8 + a_k8)) ^ arx) << 4));
            #pragma unroll
            for (int ntp = 0; ntp < 4; ntp++) {
                uint32_t Bh[4];
                ldsm_x4(Bh, st + G2_SB + bbase[ntp] + ((((uint32_t)(kh8 + b_k8)) ^ brx) << 4));
                #pragma unroll
                for (int mt = 0; mt < 2; mt++) {
                    mma16816(acc[mt][2 * ntp],     Ah[mt], Bh[0], Bh[1]);
                    mma16816(acc[mt][2 * ntp + 1], Ah[mt], Bh[2], Bh[3]);
                }
            }
        }
        cslot = (cslot == 2) ? 0 : cslot + 1;
        nslot = (nslot == 2) ? 0 : nslot + 1;
    }

    // Epilogue: weighted atomic accumulate (partial over this K half)
    #pragma unroll
    for (int mt = 0; mt < 2; mt++) {
        #pragma unroll
        for (int hrow = 0; hrow < 2; hrow++) {
            const int rr = wm * 32 + mt * 16 + g + hrow * 8;
            if (row0 + rr < nrows) {
                const int pos = start + row0 + rr;
                const int t   = g_tok[pos];
                const float w = g_wt[pos];
                float* orow = out + (size_t)t * H_DIM;
                #pragma unroll
                for (int nt = 0; nt < 8; nt++) {
                    const int col = col0 + wn * 64 + nt * 8 + tg * 2;
                    atomicAdd(orow + col,     w * acc[mt][nt][hrow * 2]);
                    atomicAdd(orow + col + 1, w * acc[mt][nt][hrow * 2 + 1]);
                }
            }
        }
    }
}

// ============================================================================
// Launch (graph-capturable: kernel launches only, 3 launches)
// ============================================================================
extern "C" void kernel_launch(void* const* d_in, const int* in_sizes, int n_in,
                              void* d_out, int out_size)
{
    const float* hidden  = (const float*)d_in[0];
    const int*   idx     = (const int*)  d_in[1];
    const float* wts     = (const float*)d_in[2];
    const float* gate_up = (const float*)d_in[3];
    const float* down    = (const float*)d_in[4];
    float*       out     = (float*)d_out;

    prep_kernel<<<PREP_BLOCKS + 1, 256>>>(gate_up, down, hidden, idx, wts, out);

    dim3 g1(I_DIM / 32, NPAIR / 128, N_EXP);        // (16, 32, 16)
    gemm1_mma<<<g1, 256, G1_TOTAL>>>();

    dim3 g2(H_DIM / 128, NPAIR / 128, N_EXP * 2);   // (8, 32, 32) — z = expert*2 + ksplit
    gemm2_mma<<<g2, 256, G2_TOTAL>>>(out);
}

// round 12
// speedup vs baseline: 1.1962x; 1.0084x over previous
#include <cuda_runtime.h>
#include <cuda_fp16.h>
#include <cstdint>
#include <math.h>

// Problem constants
#define T_TOK 1024
#define H_DIM 1024
#define I_DIM 512
#define N_EXP 16
#define TOPK  4
#define NPAIR (T_TOK * TOPK)   // 4096

// ============================================================================
// Scratch (__device__ globals; allocations are forbidden)
// ============================================================================
__device__ int   g_offset[N_EXP + 1];
__device__ int   g_tok[NPAIR];
__device__ float g_wt[NPAIR];

__device__ __half g_Xh[T_TOK * H_DIM];               // hidden, fp16
__device__ __half g_GUh[N_EXP * 2 * I_DIM * H_DIM];  // gate_up, fp16
__device__ __half g_Dh[N_EXP * H_DIM * I_DIM];       // down, fp16
__device__ __half g_Hh[NPAIR * I_DIM];               // silu(g)*u, fp16

// ============================================================================
// PTX helpers (sm_80/sm_90 baseline features — legal on plain compute_103)
// ============================================================================
__device__ __forceinline__ uint32_t smem_to_u32(const void* p) {
    uint32_t a;
    asm("{ .reg .u64 t; cvta.to.shared.u64 t, %1; cvt.u32.u64 %0, t; }" : "=r"(a) : "l"(p));
    return a;
}
__device__ __forceinline__ void cp16(uint32_t saddr, const void* g, int szbytes) {
    asm volatile("cp.async.cg.shared.global [%0], [%1], 16, %2;"
                 :: "r"(saddr), "l"(g), "r"(szbytes) : "memory");
}
#define CP_COMMIT() asm volatile("cp.async.commit_group;" ::: "memory")
#define CP_WAIT1()  asm volatile("cp.async.wait_group 1;" ::: "memory")

__device__ __forceinline__ void ldsm_x4(uint32_t* r, uint32_t addr) {
    asm volatile("ldmatrix.sync.aligned.m8n8.x4.shared.b16 {%0,%1,%2,%3}, [%4];"
                 : "=r"(r[0]), "=r"(r[1]), "=r"(r[2]), "=r"(r[3]) : "r"(addr));
}
__device__ __forceinline__ void mma16816(float* c, const uint32_t* a, uint32_t b0, uint32_t b1) {
    asm volatile(
        "mma.sync.aligned.m16n8k16.row.col.f32.f16.f16.f32 "
        "{%0,%1,%2,%3}, {%4,%5,%6,%7}, {%8,%9}, {%0,%1,%2,%3};"
        : "+f"(c[0]), "+f"(c[1]), "+f"(c[2]), "+f"(c[3])
        : "r"(a[0]), "r"(a[1]), "r"(a[2]), "r"(a[3]), "r"(b0), "r"(b1));
}
__device__ __forceinline__ void red_add_v2(float* gptr, float a, float b) {
    asm volatile("red.global.add.v2.f32 [%0], {%1, %2};"
                 :: "l"(gptr), "f"(a), "f"(b) : "memory");
}

// Tile smem rows are 64B (32 fp16), 4x16B chunks, chunk' = chunk ^ (row&3)
// GEMM1 stage: A 128x32 (8KB) | B 64x32 (4KB)  = 12KB; 3-stage ring = 36KB
// GEMM2 stage: A 128x32 (8KB) | B 128x32 (8KB) = 16KB; 3-stage ring = 48KB
#define G1_SA 0
#define G1_SB 8192
#define G1_ST 12288
#define G1_TOTAL (3 * G1_ST)
#define G2_SA 0
#define G2_SB 8192
#define G2_ST 16384
#define G2_TOTAL (3 * G2_ST)

// ============================================================================
// Prep kernels.
//  prep_gux (critical path): gate_up + hidden fp16 converts + routing block
//  prep_down (side stream):  down fp16 convert + d_out zeroing
// ============================================================================
#define N4G (N_EXP * 2 * I_DIM * H_DIM / 4)   // 4194304
#define N4D (N_EXP * H_DIM * I_DIM / 4)       // 2097152
#define N4X (T_TOK * H_DIM / 4)               // 262144
#define N4O (T_TOK * H_DIM / 4)               // 262144
#define P1_BLOCKS ((N4G + N4X) / 512)         // 8704
#define P2_BLOCKS ((N4D + N4O) / 512)         // 4608

__global__ void prep_gux(const float* __restrict__ gu,
                         const float* __restrict__ x,
                         const int*   __restrict__ idx,
                         const float* __restrict__ wts) {
    const int b = blockIdx.x;
    const int tid = threadIdx.x;

    if (b == P1_BLOCKS) {
        __shared__ int cnt[N_EXP];
        __shared__ int off[N_EXP];
        if (tid < N_EXP) cnt[tid] = 0;
        __syncthreads();
        #pragma unroll
        for (int j = 0; j < NPAIR / 256; j++)
            atomicAdd(&cnt[idx[tid + j * 256]], 1);
        __syncthreads();
        if (tid == 0) {
            int acc = 0;
            for (int e = 0; e < N_EXP; e++) { off[e] = acc; g_offset[e] = acc; acc += cnt[e]; }
            g_offset[N_EXP] = acc;
        }
        __syncthreads();
        if (tid < N_EXP) cnt[tid] = 0;
        __syncthreads();
        #pragma unroll
        for (int j = 0; j < NPAIR / 256; j++) {
            const int i = tid + j * 256;
            const int e = idx[i];
            const int pos = off[e] + atomicAdd(&cnt[e], 1);
            g_tok[pos] = i >> 2;
            g_wt[pos]  = wts[i];
        }
        return;
    }

    const int i = (b * 256 + tid) * 2;
    const float* src;
    __half* hi;
    int j;
    if (i < N4G) { src = gu; j = i;       hi = g_GUh; }
    else         { src = x;  j = i - N4G; hi = g_Xh;  }
    #pragma unroll
    for (int q = 0; q < 2; q++) {
        float4 v = ((const float4*)src)[j + q];
        __half h0 = __float2half_rn(v.x), h1 = __float2half_rn(v.y);
        __half h2 = __float2half_rn(v.z), h3 = __float2half_rn(v.w);
        uint32_t hp0 = (uint32_t)__half_as_ushort(h0) | ((uint32_t)__half_as_ushort(h1) << 16);
        uint32_t hp1 = (uint32_t)__half_as_ushort(h2) | ((uint32_t)__half_as_ushort(h3) << 16);
        ((uint2*)hi)[j + q] = make_uint2(hp0, hp1);
    }
}

__global__ void prep_down(const float* __restrict__ dn, float* __restrict__ out) {
    const int tid = threadIdx.x;
    const int i = (blockIdx.x * 256 + tid) * 2;
    if (i < N4D) {
        #pragma unroll
        for (int q = 0; q < 2; q++) {
            float4 v = ((const float4*)dn)[i + q];
            __half h0 = __float2half_rn(v.x), h1 = __float2half_rn(v.y);
            __half h2 = __float2half_rn(v.z), h3 = __float2half_rn(v.w);
            uint32_t hp0 = (uint32_t)__half_as_ushort(h0) | ((uint32_t)__half_as_ushort(h1) << 16);
            uint32_t hp1 = (uint32_t)__half_as_ushort(h2) | ((uint32_t)__half_as_ushort(h3) << 16);
            ((uint2*)g_Dh)[i + q] = make_uint2(hp0, hp1);
        }
    } else {
        const int j = i - N4D;
        ((float4*)out)[j]     = make_float4(0.f, 0.f, 0.f, 0.f);
        ((float4*)out)[j + 1] = make_float4(0.f, 0.f, 0.f, 0.f);
    }
}

// ============================================================================
// GEMM1: 128 pairs x 32 I-cols (gate/up interleaved as 64 B-rows), K = 1024
// Single-pass fp16, ldmatrix, 3-stage ring. Fused silu epilogue -> g_Hh.
// ============================================================================
__global__ __launch_bounds__(256, 3) void gemm1_mma() {
    const int e     = blockIdx.z;
    const int start = g_offset[e];
    const int nrows = g_offset[e + 1] - start;
    const int row0  = blockIdx.y * 128;
    if (row0 >= nrows) return;
    const int col0 = blockIdx.x * 32;

    extern __shared__ char smem[];
    const uint32_t sbu = smem_to_u32(smem);
    const int tid  = threadIdx.x;
    const int wid  = tid >> 5, lane = tid & 31;
    const int g    = lane >> 2, tg = lane & 3;
    const int wm   = wid & 3, wn = wid >> 2;

    const int lr = tid >> 1;
    const int lc = (tid & 1) * 2;
    const bool v0 = (row0 + lr) < nrows;
    const int tok0 = v0 ? g_tok[start + row0 + lr] : 0;
    const __half* aptr = g_Xh + (size_t)tok0 * H_DIM;
    uint32_t soA[2];
    #pragma unroll
    for (int j = 0; j < 2; j++) soA[j] = (uint32_t)(lr * 64 + (((lc + j) ^ (lr & 3)) << 4));

    const int nb = tid >> 2, cb = tid & 3;
    const size_t brow = ((size_t)e * 1024 + col0 + (nb >> 1) + (nb & 1) * 512) * H_DIM;
    const uint32_t soB = (uint32_t)(nb * 64 + ((cb ^ (nb & 3)) << 4));

    const int quad = lane >> 3, lr8 = lane & 7;
    const int a_r  = wm * 32 + (quad & 1) * 8 + lr8;
    const int a_k8 = quad >> 1;
    const int b_rb = wn * 32 + (quad >> 1) * 8 + lr8;
    const int b_k8 = quad & 1;
    const uint32_t arx = (uint32_t)(a_r & 3);
    const uint32_t brx = (uint32_t)(b_rb & 3);
    uint32_t abase[2], bbase[2];
    #pragma unroll
    for (int mt = 0; mt < 2; mt++) abase[mt] = (uint32_t)((a_r + mt * 16) * 64);
    #pragma unroll
    for (int ntp = 0; ntp < 2; ntp++) bbase[ntp] = (uint32_t)((b_rb + ntp * 16) * 64);

    float acc[2][4][4];
    #pragma unroll
    for (int a = 0; a < 2; a++)
        #pragma unroll
        for (int b = 0; b < 4; b++)
            #pragma unroll
            for (int c = 0; c < 4; c++) acc[a][b][c] = 0.f;

    const int NCH = H_DIM / 32;   // 32
    #pragma unroll
    for (int s = 0; s < 2; s++) {
        uint32_t sb = sbu + s * G1_ST;
        #pragma unroll
        for (int j = 0; j < 2; j++)
            cp16(sb + G1_SA + soA[j], aptr + s * 32 + (lc + j) * 8, v0 ? 16 : 0);
        cp16(sb + G1_SB + soB, g_GUh + brow + s * 32 + cb * 8, 16);
        CP_COMMIT();
    }

    int cslot = 0, nslot = 2;
    #pragma unroll 1
    for (int ch = 0; ch < NCH; ch++) {
        CP_WAIT1();
        __syncthreads();
        {
            const int nc = ch + 2;
            if (nc < NCH) {
                uint32_t sb = sbu + nslot * G1_ST;
                #pragma unroll
                for (int j = 0; j < 2; j++)
                    cp16(sb + G1_SA + soA[j], aptr + nc * 32 + (lc + j) * 8, v0 ? 16 : 0);
                cp16(sb + G1_SB + soB, g_GUh + brow + nc * 32 + cb * 8, 16);
            }
            CP_COMMIT();
        }
        const uint32_t st = sbu + cslot * G1_ST;
        #pragma unroll
        for (int kh8 = 0; kh8 < 4; kh8 += 2) {
            uint32_t Ah[2][4];
            #pragma unroll
            for (int mt = 0; mt < 2; mt++)
                ldsm_x4(Ah[mt], st + G1_SA + abase[mt] + ((((uint32_t)(kh8 + a_k8)) ^ arx) << 4));
            #pragma unroll
            for (int ntp = 0; ntp < 2; ntp++) {
                uint32_t Bh[4];
                ldsm_x4(Bh, st + G1_SB + bbase[ntp] + ((((uint32_t)(kh8 + b_k8)) ^ brx) << 4));
                #pragma unroll
                for (int mt = 0; mt < 2; mt++) {
                    mma16816(acc[mt][2 * ntp],     Ah[mt], Bh[0], Bh[1]);
                    mma16816(acc[mt][2 * ntp + 1], Ah[mt], Bh[2], Bh[3]);
                }
            }
        }
        cslot = (cslot == 2) ? 0 : cslot + 1;
        nslot = (nslot == 2) ? 0 : nslot + 1;
    }

    #pragma unroll
    for (int mt = 0; mt < 2; mt++) {
        #pragma unroll
        for (int nt = 0; nt < 4; nt++) {
            const int r  = wm * 32 + mt * 16 + g;
            const int jj = col0 + ((wn * 32 + nt * 8 + tg * 2) >> 1);
            const float* c = acc[mt][nt];
            #pragma unroll
            for (int hrow = 0; hrow < 2; hrow++) {
                const int rr = r + hrow * 8;
                if (row0 + rr < nrows) {
                    const float gate = c[hrow * 2], up = c[hrow * 2 + 1];
                    const float h = gate / (1.f + __expf(-gate)) * up;
                    g_Hh[(size_t)(start + row0 + rr) * I_DIM + jj] = __float2half_rn(h);
                }
            }
        }
    }
}

// ============================================================================
// GEMM2: 128 pairs x 128 H-cols, split-K x2, single-pass fp16.
// Epilogue: red.global.add.v2.f32 (out += w * partial) — vectorized atomics.
// ============================================================================
__global__ __launch_bounds__(256, 3) void gemm2_mma(float* __restrict__ out) {
    const int e     = blockIdx.z >> 1;
    const int ks    = blockIdx.z & 1;
    const int start = g_offset[e];
    const int nrows = g_offset[e + 1] - start;
    const int row0  = blockIdx.y * 128;
    if (row0 >= nrows) return;
    const int col0 = blockIdx.x * 128;
    const int kofs = ks * 256;

    extern __shared__ char smem[];
    const uint32_t sbu = smem_to_u32(smem);
    const int tid  = threadIdx.x;
    const int wid  = tid >> 5, lane = tid & 31;
    const int g    = lane >> 2, tg = lane & 3;
    const int wm   = wid & 3, wn = wid >> 2;

    const int lr = tid >> 1;
    const int lc = (tid & 1) * 2;
    const bool v0 = (row0 + lr) < nrows;
    const size_t arow = (size_t)(start + row0 + (v0 ? lr : 0)) * I_DIM;
    const size_t brow = ((size_t)e * H_DIM + col0 + lr) * I_DIM;
    uint32_t so[2];
    #pragma unroll
    for (int j = 0; j < 2; j++) so[j] = (uint32_t)(lr * 64 + (((lc + j) ^ (lr & 3)) << 4));

    const int quad = lane >> 3, lr8 = lane & 7;
    const int a_r  = wm * 32 + (quad & 1) * 8 + lr8;
    const int a_k8 = quad >> 1;
    const int b_rb = wn * 64 + (quad >> 1) * 8 + lr8;
    const int b_k8 = quad & 1;
    const uint32_t arx = (uint32_t)(a_r & 3);
    const uint32_t brx = (uint32_t)(b_rb & 3);
    uint32_t abase[2], bbase[4];
    #pragma unroll
    for (int mt = 0; mt < 2; mt++) abase[mt] = (uint32_t)((a_r + mt * 16) * 64);
    #pragma unroll
    for (int ntp = 0; ntp < 4; ntp++) bbase[ntp] = (uint32_t)((b_rb + ntp * 16) * 64);

    float acc[2][8][4];
    #pragma unroll
    for (int a = 0; a < 2; a++)
        #pragma unroll
        for (int b = 0; b < 8; b++)
            #pragma unroll
            for (int c = 0; c < 4; c++) acc[a][b][c] = 0.f;

    const int NCH = 256 / 32;   // 8
    #pragma unroll
    for (int s = 0; s < 2; s++) {
        uint32_t sb = sbu + s * G2_ST;
        #pragma unroll
        for (int j = 0; j < 2; j++) {
            const int eo = kofs + s * 32 + (lc + j) * 8;
            cp16(sb + G2_SA + so[j], g_Hh + arow + eo, v0 ? 16 : 0);
            cp16(sb + G2_SB + so[j], g_Dh + brow + eo, 16);
        }
        CP_COMMIT();
    }

    int cslot = 0, nslot = 2;
    #pragma unroll 1
    for (int ch = 0; ch < NCH; ch++) {
        CP_WAIT1();
        __syncthreads();
        {
            const int nc = ch + 2;
            if (nc < NCH) {
                uint32_t sb = sbu + nslot * G2_ST;
                #pragma unroll
                for (int j = 0; j < 2; j++) {
                    const int eo = kofs + nc * 32 + (lc + j) * 8;
                    cp16(sb + G2_SA + so[j], g_Hh + arow + eo, v0 ? 16 : 0);
                    cp16(sb + G2_SB + so[j], g_Dh + brow + eo, 16);
                }
            }
            CP_COMMIT();
        }
        const uint32_t st = sbu + cslot * G2_ST;
        #pragma unroll
        for (int kh8 = 0; kh8 < 4; kh8 += 2) {
            uint32_t Ah[2][4];
            #pragma unroll
            for (int mt = 0; mt < 2; mt++)
                ldsm_x4(Ah[mt], st + G2_SA + abase[mt] + ((((uint32_t)(kh8 + a_k8)) ^ arx) << 4));
            #pragma unroll
            for (int ntp = 0; ntp < 4; ntp++) {
                uint32_t Bh[4];
                ldsm_x4(Bh, st + G2_SB + bbase[ntp] + ((((uint32_t)(kh8 + b_k8)) ^ brx) << 4));
                #pragma unroll
                for (int mt = 0; mt < 2; mt++) {
                    mma16816(acc[mt][2 * ntp],     Ah[mt], Bh[0], Bh[1]);
                    mma16816(acc[mt][2 * ntp + 1], Ah[mt], Bh[2], Bh[3]);
                }
            }
        }
        cslot = (cslot == 2) ? 0 : cslot + 1;
        nslot = (nslot == 2) ? 0 : nslot + 1;
    }

    // Epilogue: weighted vectorized reduction into out[t, :]
    #pragma unroll
    for (int mt = 0; mt < 2; mt++) {
        #pragma unroll
        for (int hrow = 0; hrow < 2; hrow++) {
            const int rr = wm * 32 + mt * 16 + g + hrow * 8;
            if (row0 + rr < nrows) {
                const int pos = start + row0 + rr;
                const int t   = g_tok[pos];
                const float w = g_wt[pos];
                float* orow = out + (size_t)t * H_DIM;
                #pragma unroll
                for (int nt = 0; nt < 8; nt++) {
                    const int col = col0 + wn * 64 + nt * 8 + tg * 2;
                    red_add_v2(orow + col, w * acc[mt][nt][hrow * 2],
                                           w * acc[mt][nt][hrow * 2 + 1]);
                }
            }
        }
    }
}

// ============================================================================
// Launch (graph-capturable; dual-stream overlap via events)
// ============================================================================
extern "C" void kernel_launch(void* const* d_in, const int* in_sizes, int n_in,
                              void* d_out, int out_size)
{
    const float* hidden  = (const float*)d_in[0];
    const int*   idx     = (const int*)  d_in[1];
    const float* wts     = (const float*)d_in[2];
    const float* gate_up = (const float*)d_in[3];
    const float* down    = (const float*)d_in[4];
    float*       out     = (float*)d_out;

    static cudaStream_t s2 = nullptr;
    static cudaEvent_t evFork = nullptr, evJoin = nullptr;
    if (!s2) {
        cudaStreamCreateWithFlags(&s2, cudaStreamNonBlocking);
        cudaEventCreateWithFlags(&evFork, cudaEventDisableTiming);
        cudaEventCreateWithFlags(&evJoin, cudaEventDisableTiming);
    }

    // Fork side stream into the capture graph.
    cudaEventRecord(evFork, 0);
    cudaStreamWaitEvent(s2, evFork, 0);

    // Side stream: down conversion + output zeroing (needed only by gemm2).
    prep_down<<<P2_BLOCKS, 256, 0, s2>>>(down, out);
    cudaEventRecord(evJoin, s2);

    // Critical path: gate_up + hidden conversion + routing, then GEMM1.
    prep_gux<<<P1_BLOCKS + 1, 256>>>(gate_up, hidden, idx, wts);

    dim3 g1(I_DIM / 32, NPAIR / 128, N_EXP);        // (16, 32, 16)
    gemm1_mma<<<g1, 256, G1_TOTAL>>>();

    // Join before GEMM2 (needs g_Dh and zeroed out).
    cudaStreamWaitEvent(0, evJoin, 0);
    dim3 g2(H_DIM / 128, NPAIR / 128, N_EXP * 2);   // (8, 32, 32)
    gemm2_mma<<<g2, 256, G2_TOTAL>>>(out);
}

// round 14
// speedup vs baseline: 1.2016x; 1.0045x over previous
#include <cuda_runtime.h>
#include <cuda_fp16.h>
#include <cstdint>
#include <math.h>

// Problem constants
#define T_TOK 1024
#define H_DIM 1024
#define I_DIM 512
#define N_EXP 16
#define TOPK  4
#define NPAIR (T_TOK * TOPK)   // 4096

// ============================================================================
// Scratch (__device__ globals; allocations are forbidden)
// ============================================================================
__device__ int   g_offset[N_EXP + 1];
__device__ int   g_tok[NPAIR];
__device__ float g_wt[NPAIR];

__device__ __half g_Xh[T_TOK * H_DIM];               // hidden, fp16
__device__ __half g_GUh[N_EXP * 2 * I_DIM * H_DIM];  // gate_up, fp16
__device__ __half g_Dh[N_EXP * H_DIM * I_DIM];       // down, fp16
__device__ __half g_Hh[NPAIR * I_DIM];               // silu(g)*u, fp16

// ============================================================================
// PTX helpers (sm_80/sm_90 baseline features — legal on plain compute_103)
// ============================================================================
__device__ __forceinline__ uint32_t smem_to_u32(const void* p) {
    uint32_t a;
    asm("{ .reg .u64 t; cvta.to.shared.u64 t, %1; cvt.u32.u64 %0, t; }" : "=r"(a) : "l"(p));
    return a;
}
__device__ __forceinline__ void cp16(uint32_t saddr, const void* g, int szbytes) {
    asm volatile("cp.async.cg.shared.global [%0], [%1], 16, %2;"
                 :: "r"(saddr), "l"(g), "r"(szbytes) : "memory");
}
#define CP_COMMIT() asm volatile("cp.async.commit_group;" ::: "memory")
#define CP_WAIT1()  asm volatile("cp.async.wait_group 1;" ::: "memory")

__device__ __forceinline__ void ldsm_x4(uint32_t* r, uint32_t addr) {
    asm volatile("ldmatrix.sync.aligned.m8n8.x4.shared.b16 {%0,%1,%2,%3}, [%4];"
                 : "=r"(r[0]), "=r"(r[1]), "=r"(r[2]), "=r"(r[3]) : "r"(addr));
}
__device__ __forceinline__ void mma16816(float* c, const uint32_t* a, uint32_t b0, uint32_t b1) {
    asm volatile(
        "mma.sync.aligned.m16n8k16.row.col.f32.f16.f16.f32 "
        "{%0,%1,%2,%3}, {%4,%5,%6,%7}, {%8,%9}, {%0,%1,%2,%3};"
        : "+f"(c[0]), "+f"(c[1]), "+f"(c[2]), "+f"(c[3])
        : "r"(a[0]), "r"(a[1]), "r"(a[2]), "r"(a[3]), "r"(b0), "r"(b1));
}
__device__ __forceinline__ void red_add_v2(float* gptr, float a, float b) {
    asm volatile("red.global.add.v2.f32 [%0], {%1, %2};"
                 :: "l"(gptr), "f"(a), "f"(b) : "memory");
}

// Tile smem rows are 64B (32 fp16), 4x16B chunks, chunk' = chunk ^ (row&3)
// GEMM1 stage: A 64x32 (4KB) | B 64x32 (4KB)   = 8KB;  3-stage ring = 24KB
// GEMM2 stage: A 64x32 (4KB) | B 128x32 (8KB)  = 12KB; 3-stage ring = 36KB
#define G1_SA 0
#define G1_SB 4096
#define G1_ST 8192
#define G1_TOTAL (3 * G1_ST)
#define G2_SA 0
#define G2_SB 4096
#define G2_ST 12288
#define G2_TOTAL (3 * G2_ST)

// ============================================================================
// Prep kernels.
//  prep_gux (critical path): gate_up + hidden fp16 converts + routing block
//  prep_down (side stream):  down fp16 convert + d_out zeroing
// ============================================================================
#define N4G (N_EXP * 2 * I_DIM * H_DIM / 4)   // 4194304
#define N4D (N_EXP * H_DIM * I_DIM / 4)       // 2097152
#define N4X (T_TOK * H_DIM / 4)               // 262144
#define N4O (T_TOK * H_DIM / 4)               // 262144
#define P1_BLOCKS ((N4G + N4X) / 512)         // 8704
#define P2_BLOCKS ((N4D + N4O) / 512)         // 4608

__global__ void prep_gux(const float* __restrict__ gu,
                         const float* __restrict__ x,
                         const int*   __restrict__ idx,
                         const float* __restrict__ wts) {
    const int b = blockIdx.x;
    const int tid = threadIdx.x;

    if (b == P1_BLOCKS) {
        __shared__ int cnt[N_EXP];
        __shared__ int off[N_EXP];
        if (tid < N_EXP) cnt[tid] = 0;
        __syncthreads();
        #pragma unroll
        for (int j = 0; j < NPAIR / 256; j++)
            atomicAdd(&cnt[idx[tid + j * 256]], 1);
        __syncthreads();
        if (tid == 0) {
            int acc = 0;
            for (int e = 0; e < N_EXP; e++) { off[e] = acc; g_offset[e] = acc; acc += cnt[e]; }
            g_offset[N_EXP] = acc;
        }
        __syncthreads();
        if (tid < N_EXP) cnt[tid] = 0;
        __syncthreads();
        #pragma unroll
        for (int j = 0; j < NPAIR / 256; j++) {
            const int i = tid + j * 256;
            const int e = idx[i];
            const int pos = off[e] + atomicAdd(&cnt[e], 1);
            g_tok[pos] = i >> 2;
            g_wt[pos]  = wts[i];
        }
        return;
    }

    const int i = (b * 256 + tid) * 2;
    const float* src;
    __half* hi;
    int j;
    if (i < N4G) { src = gu; j = i;       hi = g_GUh; }
    else         { src = x;  j = i - N4G; hi = g_Xh;  }
    #pragma unroll
    for (int q = 0; q < 2; q++) {
        float4 v = ((const float4*)src)[j + q];
        __half h0 = __float2half_rn(v.x), h1 = __float2half_rn(v.y);
        __half h2 = __float2half_rn(v.z), h3 = __float2half_rn(v.w);
        uint32_t hp0 = (uint32_t)__half_as_ushort(h0) | ((uint32_t)__half_as_ushort(h1) << 16);
        uint32_t hp1 = (uint32_t)__half_as_ushort(h2) | ((uint32_t)__half_as_ushort(h3) << 16);
        ((uint2*)hi)[j + q] = make_uint2(hp0, hp1);
    }
}

__global__ void prep_down(const float* __restrict__ dn, float* __restrict__ out) {
    const int tid = threadIdx.x;
    const int i = (blockIdx.x * 256 + tid) * 2;
    if (i < N4D) {
        #pragma unroll
        for (int q = 0; q < 2; q++) {
            float4 v = ((const float4*)dn)[i + q];
            __half h0 = __float2half_rn(v.x), h1 = __float2half_rn(v.y);
            __half h2 = __float2half_rn(v.z), h3 = __float2half_rn(v.w);
            uint32_t hp0 = (uint32_t)__half_as_ushort(h0) | ((uint32_t)__half_as_ushort(h1) << 16);
            uint32_t hp1 = (uint32_t)__half_as_ushort(h2) | ((uint32_t)__half_as_ushort(h3) << 16);
            ((uint2*)g_Dh)[i + q] = make_uint2(hp0, hp1);
        }
    } else {
        const int j = i - N4D;
        ((float4*)out)[j]     = make_float4(0.f, 0.f, 0.f, 0.f);
        ((float4*)out)[j + 1] = make_float4(0.f, 0.f, 0.f, 0.f);
    }
}

// ============================================================================
// GEMM1: 64 pairs x 32 I-cols (gate/up interleaved as 64 B-rows), K = 1024
// 128-thread CTA (2 warps M x 2 warps N), ldsm, 3-stage ring, fused silu.
// ============================================================================
__global__ __launch_bounds__(128, 8) void gemm1_mma() {
    const int e     = blockIdx.z;
    const int start = g_offset[e];
    const int nrows = g_offset[e + 1] - start;
    const int row0  = blockIdx.y * 64;
    if (row0 >= nrows) return;
    const int col0 = blockIdx.x * 32;

    extern __shared__ char smem[];
    const uint32_t sbu = smem_to_u32(smem);
    const int tid  = threadIdx.x;
    const int wid  = tid >> 5, lane = tid & 31;
    const int g    = lane >> 2, tg = lane & 3;
    const int wm   = wid & 1, wn = wid >> 1;   // 2 warps M(32) x 2 warps N(32 B-rows)

    // A loader: thread t owns row lr = t>>1 (0..63), chunks lc, lc+1
    const int lr = tid >> 1;
    const int lc = (tid & 1) * 2;
    const bool v0 = (row0 + lr) < nrows;
    const int tok0 = v0 ? g_tok[start + row0 + lr] : 0;
    const __half* aptr = g_Xh + (size_t)tok0 * H_DIM;
    uint32_t soA[2];
    #pragma unroll
    for (int j = 0; j < 2; j++) soA[j] = (uint32_t)(lr * 64 + (((lc + j) ^ (lr & 3)) << 4));

    // B loader: same row mapping (64 B-rows)
    const size_t brow = ((size_t)e * 1024 + col0 + (lr >> 1) + (lr & 1) * 512) * H_DIM;

    // mma lane geometry (ldmatrix addressing)
    const int quad = lane >> 3, lr8 = lane & 7;
    const int a_r  = wm * 32 + (quad & 1) * 8 + lr8;   // + mt*16
    const int a_k8 = quad >> 1;
    const int b_rb = wn * 32 + (quad >> 1) * 8 + lr8;  // + ntp*16
    const int b_k8 = quad & 1;
    const uint32_t arx = (uint32_t)(a_r & 3);
    const uint32_t brx = (uint32_t)(b_rb & 3);
    uint32_t abase[2], bbase[2];
    #pragma unroll
    for (int mt = 0; mt < 2; mt++) abase[mt] = (uint32_t)((a_r + mt * 16) * 64);
    #pragma unroll
    for (int ntp = 0; ntp < 2; ntp++) bbase[ntp] = (uint32_t)((b_rb + ntp * 16) * 64);

    float acc[2][4][4];
    #pragma unroll
    for (int a = 0; a < 2; a++)
        #pragma unroll
        for (int b = 0; b < 4; b++)
            #pragma unroll
            for (int c = 0; c < 4; c++) acc[a][b][c] = 0.f;

    const int NCH = H_DIM / 32;   // 32
    #pragma unroll
    for (int s = 0; s < 2; s++) {
        uint32_t sb = sbu + s * G1_ST;
        #pragma unroll
        for (int j = 0; j < 2; j++) {
            cp16(sb + G1_SA + soA[j], aptr + s * 32 + (lc + j) * 8, v0 ? 16 : 0);
            cp16(sb + G1_SB + soA[j], g_GUh + brow + s * 32 + (lc + j) * 8, 16);
        }
        CP_COMMIT();
    }

    int cslot = 0, nslot = 2;
    #pragma unroll 1
    for (int ch = 0; ch < NCH; ch++) {
        CP_WAIT1();
        __syncthreads();
        {
            const int nc = ch + 2;
            if (nc < NCH) {
                uint32_t sb = sbu + nslot * G1_ST;
                #pragma unroll
                for (int j = 0; j < 2; j++) {
                    cp16(sb + G1_SA + soA[j], aptr + nc * 32 + (lc + j) * 8, v0 ? 16 : 0);
                    cp16(sb + G1_SB + soA[j], g_GUh + brow + nc * 32 + (lc + j) * 8, 16);
                }
            }
            CP_COMMIT();
        }
        const uint32_t st = sbu + cslot * G1_ST;
        #pragma unroll
        for (int kh8 = 0; kh8 < 4; kh8 += 2) {
            uint32_t Ah[2][4];
            #pragma unroll
            for (int mt = 0; mt < 2; mt++)
                ldsm_x4(Ah[mt], st + G1_SA + abase[mt] + ((((uint32_t)(kh8 + a_k8)) ^ arx) << 4));
            #pragma unroll
            for (int ntp = 0; ntp < 2; ntp++) {
                uint32_t Bh[4];
                ldsm_x4(Bh, st + G1_SB + bbase[ntp] + ((((uint32_t)(kh8 + b_k8)) ^ brx) << 4));
                #pragma unroll
                for (int mt = 0; mt < 2; mt++) {
                    mma16816(acc[mt][2 * ntp],     Ah[mt], Bh[0], Bh[1]);
                    mma16816(acc[mt][2 * ntp + 1], Ah[mt], Bh[2], Bh[3]);
                }
            }
        }
        cslot = (cslot == 2) ? 0 : cslot + 1;
        nslot = (nslot == 2) ? 0 : nslot + 1;
    }

    // Epilogue: (c0,c1)=(gate,up) of one logical col; silu fuse; fp16 store.
    #pragma unroll
    for (int mt = 0; mt < 2; mt++) {
        #pragma unroll
        for (int nt = 0; nt < 4; nt++) {
            const int r  = wm * 32 + mt * 16 + g;
            const int jj = col0 + ((wn * 32 + nt * 8 + tg * 2) >> 1);
            const float* c = acc[mt][nt];
            #pragma unroll
            for (int hrow = 0; hrow < 2; hrow++) {
                const int rr = r + hrow * 8;
                if (row0 + rr < nrows) {
                    const float gate = c[hrow * 2], up = c[hrow * 2 + 1];
                    const float h = gate / (1.f + __expf(-gate)) * up;
                    g_Hh[(size_t)(start + row0 + rr) * I_DIM + jj] = __float2half_rn(h);
                }
            }
        }
    }
}

// ============================================================================
// GEMM2: 64 pairs x 128 H-cols, split-K x2 (256 each), single-pass fp16.
// 128-thread CTA (2 warps M x 2 warps N of 64 cols). red.global.add.v2 out.
// ============================================================================
__global__ __launch_bounds__(128, 6) void gemm2_mma(float* __restrict__ out) {
    const int e     = blockIdx.z >> 1;
    const int ks    = blockIdx.z & 1;
    const int start = g_offset[e];
    const int nrows = g_offset[e + 1] - start;
    const int row0  = blockIdx.y * 64;
    if (row0 >= nrows) return;
    const int col0 = blockIdx.x * 128;
    const int kofs = ks * 256;

    extern __shared__ char smem[];
    const uint32_t sbu = smem_to_u32(smem);
    const int tid  = threadIdx.x;
    const int wid  = tid >> 5, lane = tid & 31;
    const int g    = lane >> 2, tg = lane & 3;
    const int wm   = wid & 1, wn = wid >> 1;   // 2 warps M(32) x 2 warps N(64 cols)

    // A loader: thread t>>1 = row (0..63), 2 chunks
    const int lr = tid >> 1;
    const int lc = (tid & 1) * 2;
    const bool v0 = (row0 + lr) < nrows;
    const size_t arow = (size_t)(start + row0 + (v0 ? lr : 0)) * I_DIM;
    uint32_t soA[2];
    #pragma unroll
    for (int j = 0; j < 2; j++) soA[j] = (uint32_t)(lr * 64 + (((lc + j) ^ (lr & 3)) << 4));

    // B loader: thread t = row (0..127), all 4 chunks of that row
    const size_t brow = ((size_t)e * H_DIM + col0 + tid) * I_DIM;
    uint32_t soB[4];
    #pragma unroll
    for (int j = 0; j < 4; j++) soB[j] = (uint32_t)(tid * 64 + ((j ^ (tid & 3)) << 4));

    const int quad = lane >> 3, lr8 = lane & 7;
    const int a_r  = wm * 32 + (quad & 1) * 8 + lr8;
    const int a_k8 = quad >> 1;
    const int b_rb = wn * 64 + (quad >> 1) * 8 + lr8;
    const int b_k8 = quad & 1;
    const uint32_t arx = (uint32_t)(a_r & 3);
    const uint32_t brx = (uint32_t)(b_rb & 3);
    uint32_t abase[2], bbase[4];
    #pragma unroll
    for (int mt = 0; mt < 2; mt++) abase[mt] = (uint32_t)((a_r + mt * 16) * 64);
    #pragma unroll
    for (int ntp = 0; ntp < 4; ntp++) bbase[ntp] = (uint32_t)((b_rb + ntp * 16) * 64);

    float acc[2][8][4];
    #pragma unroll
    for (int a = 0; a < 2; a++)
        #pragma unroll
        for (int b = 0; b < 8; b++)
            #pragma unroll
            for (int c = 0; c < 4; c++) acc[a][b][c] = 0.f;

    const int NCH = 256 / 32;   // 8
    #pragma unroll
    for (int s = 0; s < 2; s++) {
        uint32_t sb = sbu + s * G2_ST;
        #pragma unroll
        for (int j = 0; j < 2; j++)
            cp16(sb + G2_SA + soA[j], g_Hh + arow + kofs + s * 32 + (lc + j) * 8, v0 ? 16 : 0);
        #pragma unroll
        for (int j = 0; j < 4; j++)
            cp16(sb + G2_SB + soB[j], g_Dh + brow + kofs + s * 32 + j * 8, 16);
        CP_COMMIT();
    }

    int cslot = 0, nslot = 2;
    #pragma unroll 1
    for (int ch = 0; ch < NCH; ch++) {
        CP_WAIT1();
        __syncthreads();
        {
            const int nc = ch + 2;
            if (nc < NCH) {
                uint32_t sb = sbu + nslot * G2_ST;
                #pragma unroll
                for (int j = 0; j < 2; j++)
                    cp16(sb + G2_SA + soA[j], g_Hh + arow + kofs + nc * 32 + (lc + j) * 8, v0 ? 16 : 0);
                #pragma unroll
                for (int j = 0; j < 4; j++)
                    cp16(sb + G2_SB + soB[j], g_Dh + brow + kofs + nc * 32 + j * 8, 16);
            }
            CP_COMMIT();
        }
        const uint32_t st = sbu + cslot * G2_ST;
        #pragma unroll
        for (int kh8 = 0; kh8 < 4; kh8 += 2) {
            uint32_t Ah[2][4];
            #pragma unroll
            for (int mt = 0; mt < 2; mt++)
                ldsm_x4(Ah[mt], st + G2_SA + abase[mt] + ((((uint32_t)(kh8 + a_k8)) ^ arx) << 4));
            #pragma unroll
            for (int ntp = 0; ntp < 4; ntp++) {
                uint32_t Bh[4];
                ldsm_x4(Bh, st + G2_SB + bbase[ntp] + ((((uint32_t)(kh8 + b_k8)) ^ brx) << 4));
                #pragma unroll
                for (int mt = 0; mt < 2; mt++) {
                    mma16816(acc[mt][2 * ntp],     Ah[mt], Bh[0], Bh[1]);
                    mma16816(acc[mt][2 * ntp + 1], Ah[mt], Bh[2], Bh[3]);
                }
            }
        }
        cslot = (cslot == 2) ? 0 : cslot + 1;
        nslot = (nslot == 2) ? 0 : nslot + 1;
    }

    // Epilogue: weighted vectorized reduction into out[t, :]
    #pragma unroll
    for (int mt = 0; mt < 2; mt++) {
        #pragma unroll
        for (int hrow = 0; hrow < 2; hrow++) {
            const int rr = wm * 32 + mt * 16 + g + hrow * 8;
            if (row0 + rr < nrows) {
                const int pos = start + row0 + rr;
                const int t   = g_tok[pos];
                const float w = g_wt[pos];
                float* orow = out + (size_t)t * H_DIM;
                #pragma unroll
                for (int nt = 0; nt < 8; nt++) {
                    const int col = col0 + wn * 64 + nt * 8 + tg * 2;
                    red_add_v2(orow + col, w * acc[mt][nt][hrow * 2],
                                           w * acc[mt][nt][hrow * 2 + 1]);
                }
            }
        }
    }
}

// ============================================================================
// Launch (graph-capturable; dual-stream overlap via events)
// ============================================================================
extern "C" void kernel_launch(void* const* d_in, const int* in_sizes, int n_in,
                              void* d_out, int out_size)
{
    const float* hidden  = (const float*)d_in[0];
    const int*   idx     = (const int*)  d_in[1];
    const float* wts     = (const float*)d_in[2];
    const float* gate_up = (const float*)d_in[3];
    const float* down    = (const float*)d_in[4];
    float*       out     = (float*)d_out;

    static cudaStream_t s2 = nullptr;
    static cudaEvent_t evFork = nullptr, evJoin = nullptr;
    if (!s2) {
        cudaStreamCreateWithFlags(&s2, cudaStreamNonBlocking);
        cudaEventCreateWithFlags(&evFork, cudaEventDisableTiming);
        cudaEventCreateWithFlags(&evJoin, cudaEventDisableTiming);
    }

    // Fork side stream into the capture graph.
    cudaEventRecord(evFork, 0);
    cudaStreamWaitEvent(s2, evFork, 0);

    // Side stream: down conversion + output zeroing (needed only by gemm2).
    prep_down<<<P2_BLOCKS, 256, 0, s2>>>(down, out);
    cudaEventRecord(evJoin, s2);

    // Critical path: gate_up + hidden conversion + routing, then GEMM1.
    prep_gux<<<P1_BLOCKS + 1, 256>>>(gate_up, hidden, idx, wts);

    dim3 g1(I_DIM / 32, NPAIR / 64, N_EXP);         // (16, 64, 16)
    gemm1_mma<<<g1, 128, G1_TOTAL>>>();

    // Join before GEMM2 (needs g_Dh and zeroed out).
    cudaStreamWaitEvent(0, evJoin, 0);
    dim3 g2(H_DIM / 128, NPAIR / 64, N_EXP * 2);    // (8, 64, 32)
    gemm2_mma<<<g2, 128, G2_TOTAL>>>(out);
}

// round 15
// speedup vs baseline: 1.2686x; 1.0558x over previous
#include <cuda_runtime.h>
#include <cuda_fp16.h>
#include <cstdint>
#include <math.h>

// Problem constants
#define T_TOK 1024
#define H_DIM 1024
#define I_DIM 512
#define N_EXP 16
#define TOPK  4
#define NPAIR (T_TOK * TOPK)   // 4096

// ============================================================================
// Scratch (__device__ globals; allocations are forbidden)
// ============================================================================
__device__ int   g_offset[N_EXP + 1];
__device__ int   g_tok[NPAIR];
__device__ float g_wt[NPAIR];

__device__ __half g_Xh[T_TOK * H_DIM];               // hidden, fp16
__device__ __half g_GUh[N_EXP * 2 * I_DIM * H_DIM];  // gate_up, fp16
__device__ __half g_Dh[N_EXP * H_DIM * I_DIM];       // down, fp16
__device__ __half g_Hh[NPAIR * I_DIM];               // silu(g)*u, fp16

// ============================================================================
// PTX helpers (sm_80/sm_90 baseline features — legal on plain compute_103)
// ============================================================================
__device__ __forceinline__ uint32_t smem_to_u32(const void* p) {
    uint32_t a;
    asm("{ .reg .u64 t; cvta.to.shared.u64 t, %1; cvt.u32.u64 %0, t; }" : "=r"(a) : "l"(p));
    return a;
}
__device__ __forceinline__ void cp16(uint32_t saddr, const void* g, int szbytes) {
    asm volatile("cp.async.cg.shared.global [%0], [%1], 16, %2;"
                 :: "r"(saddr), "l"(g), "r"(szbytes) : "memory");
}
#define CP_COMMIT() asm volatile("cp.async.commit_group;" ::: "memory")
#define CP_WAIT1()  asm volatile("cp.async.wait_group 1;" ::: "memory")

__device__ __forceinline__ void ldsm_x4(uint32_t* r, uint32_t addr) {
    asm volatile("ldmatrix.sync.aligned.m8n8.x4.shared.b16 {%0,%1,%2,%3}, [%4];"
                 : "=r"(r[0]), "=r"(r[1]), "=r"(r[2]), "=r"(r[3]) : "r"(addr));
}
__device__ __forceinline__ void mma16816(float* c, const uint32_t* a, uint32_t b0, uint32_t b1) {
    asm volatile(
        "mma.sync.aligned.m16n8k16.row.col.f32.f16.f16.f32 "
        "{%0,%1,%2,%3}, {%4,%5,%6,%7}, {%8,%9}, {%0,%1,%2,%3};"
        : "+f"(c[0]), "+f"(c[1]), "+f"(c[2]), "+f"(c[3])
        : "r"(a[0]), "r"(a[1]), "r"(a[2]), "r"(a[3]), "r"(b0), "r"(b1));
}
__device__ __forceinline__ void red_add_v2(float* gptr, float a, float b) {
    asm volatile("red.global.add.v2.f32 [%0], {%1, %2};"
                 :: "l"(gptr), "f"(a), "f"(b) : "memory");
}

// Tile smem rows are 64B (32 fp16), 4x16B chunks, chunk' = chunk ^ (row&3)
// GEMM1 stage: A 64x32 (4KB) | B 64x32 (4KB)   = 8KB;  3-stage ring = 24KB
// GEMM2 stage: A 128x32 (8KB) | B 128x32 (8KB) = 16KB; 3-stage ring = 48KB
#define G1_SA 0
#define G1_SB 4096
#define G1_ST 8192
#define G1_TOTAL (3 * G1_ST)
#define G2_SA 0
#define G2_SB 8192
#define G2_ST 16384
#define G2_TOTAL (3 * G2_ST)

// ============================================================================
// Prep kernels.
//  prep_gux (critical path): gate_up + hidden fp16 converts + routing block
//  prep_down (side stream):  down fp16 convert + d_out zeroing
// ============================================================================
#define N4G (N_EXP * 2 * I_DIM * H_DIM / 4)   // 4194304
#define N4D (N_EXP * H_DIM * I_DIM / 4)       // 2097152
#define N4X (T_TOK * H_DIM / 4)               // 262144
#define N4O (T_TOK * H_DIM / 4)               // 262144
#define P1_BLOCKS ((N4G + N4X) / 512)         // 8704
#define P2_BLOCKS ((N4D + N4O) / 512)         // 4608

__global__ void prep_gux(const float* __restrict__ gu,
                         const float* __restrict__ x,
                         const int*   __restrict__ idx,
                         const float* __restrict__ wts) {
    const int b = blockIdx.x;
    const int tid = threadIdx.x;

    if (b == P1_BLOCKS) {
        __shared__ int cnt[N_EXP];
        __shared__ int off[N_EXP];
        if (tid < N_EXP) cnt[tid] = 0;
        __syncthreads();
        #pragma unroll
        for (int j = 0; j < NPAIR / 256; j++)
            atomicAdd(&cnt[idx[tid + j * 256]], 1);
        __syncthreads();
        if (tid == 0) {
            int acc = 0;
            for (int e = 0; e < N_EXP; e++) { off[e] = acc; g_offset[e] = acc; acc += cnt[e]; }
            g_offset[N_EXP] = acc;
        }
        __syncthreads();
        if (tid < N_EXP) cnt[tid] = 0;
        __syncthreads();
        #pragma unroll
        for (int j = 0; j < NPAIR / 256; j++) {
            const int i = tid + j * 256;
            const int e = idx[i];
            const int pos = off[e] + atomicAdd(&cnt[e], 1);
            g_tok[pos] = i >> 2;
            g_wt[pos]  = wts[i];
        }
        return;
    }

    const int i = (b * 256 + tid) * 2;
    const float* src;
    __half* hi;
    int j;
    if (i < N4G) { src = gu; j = i;       hi = g_GUh; }
    else         { src = x;  j = i - N4G; hi = g_Xh;  }
    #pragma unroll
    for (int q = 0; q < 2; q++) {
        float4 v = ((const float4*)src)[j + q];
        __half h0 = __float2half_rn(v.x), h1 = __float2half_rn(v.y);
        __half h2 = __float2half_rn(v.z), h3 = __float2half_rn(v.w);
        uint32_t hp0 = (uint32_t)__half_as_ushort(h0) | ((uint32_t)__half_as_ushort(h1) << 16);
        uint32_t hp1 = (uint32_t)__half_as_ushort(h2) | ((uint32_t)__half_as_ushort(h3) << 16);
        ((uint2*)hi)[j + q] = make_uint2(hp0, hp1);
    }
}

__global__ void prep_down(const float* __restrict__ dn, float* __restrict__ out) {
    const int tid = threadIdx.x;
    const int i = (blockIdx.x * 256 + tid) * 2;
    if (i < N4D) {
        #pragma unroll
        for (int q = 0; q < 2; q++) {
            float4 v = ((const float4*)dn)[i + q];
            __half h0 = __float2half_rn(v.x), h1 = __float2half_rn(v.y);
            __half h2 = __float2half_rn(v.z), h3 = __float2half_rn(v.w);
            uint32_t hp0 = (uint32_t)__half_as_ushort(h0) | ((uint32_t)__half_as_ushort(h1) << 16);
            uint32_t hp1 = (uint32_t)__half_as_ushort(h2) | ((uint32_t)__half_as_ushort(h3) << 16);
            ((uint2*)g_Dh)[i + q] = make_uint2(hp0, hp1);
        }
    } else {
        const int j = i - N4D;
        ((float4*)out)[j]     = make_float4(0.f, 0.f, 0.f, 0.f);
        ((float4*)out)[j + 1] = make_float4(0.f, 0.f, 0.f, 0.f);
    }
}

// ============================================================================
// GEMM1 (R14 shape — measured best): 64 pairs x 32 I-cols, K = 1024,
// 128-thread CTA (2 warps M x 2 warps N), ldsm, 3-stage ring, fused silu.
// ============================================================================
__global__ __launch_bounds__(128, 8) void gemm1_mma() {
    const int e     = blockIdx.z;
    const int start = g_offset[e];
    const int nrows = g_offset[e + 1] - start;
    const int row0  = blockIdx.y * 64;
    if (row0 >= nrows) return;
    const int col0 = blockIdx.x * 32;

    extern __shared__ char smem[];
    const uint32_t sbu = smem_to_u32(smem);
    const int tid  = threadIdx.x;
    const int wid  = tid >> 5, lane = tid & 31;
    const int g    = lane >> 2, tg = lane & 3;
    const int wm   = wid & 1, wn = wid >> 1;

    const int lr = tid >> 1;
    const int lc = (tid & 1) * 2;
    const bool v0 = (row0 + lr) < nrows;
    const int tok0 = v0 ? g_tok[start + row0 + lr] : 0;
    const __half* aptr = g_Xh + (size_t)tok0 * H_DIM;
    uint32_t soA[2];
    #pragma unroll
    for (int j = 0; j < 2; j++) soA[j] = (uint32_t)(lr * 64 + (((lc + j) ^ (lr & 3)) << 4));

    const size_t brow = ((size_t)e * 1024 + col0 + (lr >> 1) + (lr & 1) * 512) * H_DIM;

    const int quad = lane >> 3, lr8 = lane & 7;
    const int a_r  = wm * 32 + (quad & 1) * 8 + lr8;
    const int a_k8 = quad >> 1;
    const int b_rb = wn * 32 + (quad >> 1) * 8 + lr8;
    const int b_k8 = quad & 1;
    const uint32_t arx = (uint32_t)(a_r & 3);
    const uint32_t brx = (uint32_t)(b_rb & 3);
    uint32_t abase[2], bbase[2];
    #pragma unroll
    for (int mt = 0; mt < 2; mt++) abase[mt] = (uint32_t)((a_r + mt * 16) * 64);
    #pragma unroll
    for (int ntp = 0; ntp < 2; ntp++) bbase[ntp] = (uint32_t)((b_rb + ntp * 16) * 64);

    float acc[2][4][4];
    #pragma unroll
    for (int a = 0; a < 2; a++)
        #pragma unroll
        for (int b = 0; b < 4; b++)
            #pragma unroll
            for (int c = 0; c < 4; c++) acc[a][b][c] = 0.f;

    const int NCH = H_DIM / 32;   // 32
    #pragma unroll
    for (int s = 0; s < 2; s++) {
        uint32_t sb = sbu + s * G1_ST;
        #pragma unroll
        for (int j = 0; j < 2; j++) {
            cp16(sb + G1_SA + soA[j], aptr + s * 32 + (lc + j) * 8, v0 ? 16 : 0);
            cp16(sb + G1_SB + soA[j], g_GUh + brow + s * 32 + (lc + j) * 8, 16);
        }
        CP_COMMIT();
    }

    int cslot = 0, nslot = 2;
    #pragma unroll 1
    for (int ch = 0; ch < NCH; ch++) {
        CP_WAIT1();
        __syncthreads();
        {
            const int nc = ch + 2;
            if (nc < NCH) {
                uint32_t sb = sbu + nslot * G1_ST;
                #pragma unroll
                for (int j = 0; j < 2; j++) {
                    cp16(sb + G1_SA + soA[j], aptr + nc * 32 + (lc + j) * 8, v0 ? 16 : 0);
                    cp16(sb + G1_SB + soA[j], g_GUh + brow + nc * 32 + (lc + j) * 8, 16);
                }
            }
            CP_COMMIT();
        }
        const uint32_t st = sbu + cslot * G1_ST;
        #pragma unroll
        for (int kh8 = 0; kh8 < 4; kh8 += 2) {
            uint32_t Ah[2][4];
            #pragma unroll
            for (int mt = 0; mt < 2; mt++)
                ldsm_x4(Ah[mt], st + G1_SA + abase[mt] + ((((uint32_t)(kh8 + a_k8)) ^ arx) << 4));
            #pragma unroll
            for (int ntp = 0; ntp < 2; ntp++) {
                uint32_t Bh[4];
                ldsm_x4(Bh, st + G1_SB + bbase[ntp] + ((((uint32_t)(kh8 + b_k8)) ^ brx) << 4));
                #pragma unroll
                for (int mt = 0; mt < 2; mt++) {
                    mma16816(acc[mt][2 * ntp],     Ah[mt], Bh[0], Bh[1]);
                    mma16816(acc[mt][2 * ntp + 1], Ah[mt], Bh[2], Bh[3]);
                }
            }
        }
        cslot = (cslot == 2) ? 0 : cslot + 1;
        nslot = (nslot == 2) ? 0 : nslot + 1;
    }

    #pragma unroll
    for (int mt = 0; mt < 2; mt++) {
        #pragma unroll
        for (int nt = 0; nt < 4; nt++) {
            const int r  = wm * 32 + mt * 16 + g;
            const int jj = col0 + ((wn * 32 + nt * 8 + tg * 2) >> 1);
            const float* c = acc[mt][nt];
            #pragma unroll
            for (int hrow = 0; hrow < 2; hrow++) {
                const int rr = r + hrow * 8;
                if (row0 + rr < nrows) {
                    const float gate = c[hrow * 2], up = c[hrow * 2 + 1];
                    const float h = gate / (1.f + __expf(-gate)) * up;
                    g_Hh[(size_t)(start + row0 + rr) * I_DIM + jj] = __float2half_rn(h);
                }
            }
        }
    }
}

// ============================================================================
// GEMM2 (R12 shape — measured best): 128 pairs x 128 H-cols, split-K x2,
// 256-thread CTA, single-pass fp16, 3-stage ring, red.global.add.v2 epilogue.
// ============================================================================
__global__ __launch_bounds__(256, 3) void gemm2_mma(float* __restrict__ out) {
    const int e     = blockIdx.z >> 1;
    const int ks    = blockIdx.z & 1;
    const int start = g_offset[e];
    const int nrows = g_offset[e + 1] - start;
    const int row0  = blockIdx.y * 128;
    if (row0 >= nrows) return;
    const int col0 = blockIdx.x * 128;
    const int kofs = ks * 256;

    extern __shared__ char smem[];
    const uint32_t sbu = smem_to_u32(smem);
    const int tid  = threadIdx.x;
    const int wid  = tid >> 5, lane = tid & 31;
    const int g    = lane >> 2, tg = lane & 3;
    const int wm   = wid & 3, wn = wid >> 2;

    const int lr = tid >> 1;
    const int lc = (tid & 1) * 2;
    const bool v0 = (row0 + lr) < nrows;
    const size_t arow = (size_t)(start + row0 + (v0 ? lr : 0)) * I_DIM;
    const size_t brow = ((size_t)e * H_DIM + col0 + lr) * I_DIM;
    uint32_t so[2];
    #pragma unroll
    for (int j = 0; j < 2; j++) so[j] = (uint32_t)(lr * 64 + (((lc + j) ^ (lr & 3)) << 4));

    const int quad = lane >> 3, lr8 = lane & 7;
    const int a_r  = wm * 32 + (quad & 1) * 8 + lr8;
    const int a_k8 = quad >> 1;
    const int b_rb = wn * 64 + (quad >> 1) * 8 + lr8;
    const int b_k8 = quad & 1;
    const uint32_t arx = (uint32_t)(a_r & 3);
    const uint32_t brx = (uint32_t)(b_rb & 3);
    uint32_t abase[2], bbase[4];
    #pragma unroll
    for (int mt = 0; mt < 2; mt++) abase[mt] = (uint32_t)((a_r + mt * 16) * 64);
    #pragma unroll
    for (int ntp = 0; ntp < 4; ntp++) bbase[ntp] = (uint32_t)((b_rb + ntp * 16) * 64);

    float acc[2][8][4];
    #pragma unroll
    for (int a = 0; a < 2; a++)
        #pragma unroll
        for (int b = 0; b < 8; b++)
            #pragma unroll
            for (int c = 0; c < 4; c++) acc[a][b][c] = 0.f;

    const int NCH = 256 / 32;   // 8
    #pragma unroll
    for (int s = 0; s < 2; s++) {
        uint32_t sb = sbu + s * G2_ST;
        #pragma unroll
        for (int j = 0; j < 2; j++) {
            const int eo = kofs + s * 32 + (lc + j) * 8;
            cp16(sb + G2_SA + so[j], g_Hh + arow + eo, v0 ? 16 : 0);
            cp16(sb + G2_SB + so[j], g_Dh + brow + eo, 16);
        }
        CP_COMMIT();
    }

    int cslot = 0, nslot = 2;
    #pragma unroll 1
    for (int ch = 0; ch < NCH; ch++) {
        CP_WAIT1();
        __syncthreads();
        {
            const int nc = ch + 2;
            if (nc < NCH) {
                uint32_t sb = sbu + nslot * G2_ST;
                #pragma unroll
                for (int j = 0; j < 2; j++) {
                    const int eo = kofs + nc * 32 + (lc + j) * 8;
                    cp16(sb + G2_SA + so[j], g_Hh + arow + eo, v0 ? 16 : 0);
                    cp16(sb + G2_SB + so[j], g_Dh + brow + eo, 16);
                }
            }
            CP_COMMIT();
        }
        const uint32_t st = sbu + cslot * G2_ST;
        #pragma unroll
        for (int kh8 = 0; kh8 < 4; kh8 += 2) {
            uint32_t Ah[2][4];
            #pragma unroll
            for (int mt = 0; mt < 2; mt++)
                ldsm_x4(Ah[mt], st + G2_SA + abase[mt] + ((((uint32_t)(kh8 + a_k8)) ^ arx) << 4));
            #pragma unroll
            for (int ntp = 0; ntp < 4; ntp++) {
                uint32_t Bh[4];
                ldsm_x4(Bh, st + G2_SB + bbase[ntp] + ((((uint32_t)(kh8 + b_k8)) ^ brx) << 4));
                #pragma unroll
                for (int mt = 0; mt < 2; mt++) {
                    mma16816(acc[mt][2 * ntp],     Ah[mt], Bh[0], Bh[1]);
                    mma16816(acc[mt][2 * ntp + 1], Ah[mt], Bh[2], Bh[3]);
                }
            }
        }
        cslot = (cslot == 2) ? 0 : cslot + 1;
        nslot = (nslot == 2) ? 0 : nslot + 1;
    }

    // Epilogue: weighted vectorized reduction into out[t, :]
    #pragma unroll
    for (int mt = 0; mt < 2; mt++) {
        #pragma unroll
        for (int hrow = 0; hrow < 2; hrow++) {
            const int rr = wm * 32 + mt * 16 + g + hrow * 8;
            if (row0 + rr < nrows) {
                const int pos = start + row0 + rr;
                const int t   = g_tok[pos];
                const float w = g_wt[pos];
                float* orow = out + (size_t)t * H_DIM;
                #pragma unroll
                for (int nt = 0; nt < 8; nt++) {
                    const int col = col0 + wn * 64 + nt * 8 + tg * 2;
                    red_add_v2(orow + col, w * acc[mt][nt][hrow * 2],
                                           w * acc[mt][nt][hrow * 2 + 1]);
                }
            }
        }
    }
}

// ============================================================================
// Launch (graph-capturable; dual-stream overlap via events)
// ============================================================================
extern "C" void kernel_launch(void* const* d_in, const int* in_sizes, int n_in,
                              void* d_out, int out_size)
{
    const float* hidden  = (const float*)d_in[0];
    const int*   idx     = (const int*)  d_in[1];
    const float* wts     = (const float*)d_in[2];
    const float* gate_up = (const float*)d_in[3];
    const float* down    = (const float*)d_in[4];
    float*       out     = (float*)d_out;

    static cudaStream_t s2 = nullptr;
    static cudaEvent_t evFork = nullptr, evJoin = nullptr;
    if (!s2) {
        cudaStreamCreateWithFlags(&s2, cudaStreamNonBlocking);
        cudaEventCreateWithFlags(&evFork, cudaEventDisableTiming);
        cudaEventCreateWithFlags(&evJoin, cudaEventDisableTiming);
    }

    // Fork side stream into the capture graph.
    cudaEventRecord(evFork, 0);
    cudaStreamWaitEvent(s2, evFork, 0);

    // Side stream: down conversion + output zeroing (needed only by gemm2).
    prep_down<<<P2_BLOCKS, 256, 0, s2>>>(down, out);
    cudaEventRecord(evJoin, s2);

    // Critical path: gate_up + hidden conversion + routing, then GEMM1.
    prep_gux<<<P1_BLOCKS + 1, 256>>>(gate_up, hidden, idx, wts);

    dim3 g1(I_DIM / 32, NPAIR / 64, N_EXP);         // (16, 64, 16)
    gemm1_mma<<<g1, 128, G1_TOTAL>>>();

    // Join before GEMM2 (needs g_Dh and zeroed out).
    cudaStreamWaitEvent(0, evJoin, 0);
    dim3 g2(H_DIM / 128, NPAIR / 128, N_EXP * 2);   // (8, 32, 32)
    gemm2_mma<<<g2, 256, G2_TOTAL>>>(out);
}